// round 12
// baseline (speedup 1.0000x reference)
#include <cuda_runtime.h>
#include <cuda_bf16.h>
#include <math.h>
#include <stdint.h>

#define H   32
#define SEQ 2048
#define DH  128
#define NOUT 16
#define QMAXF 7.0f

// ---------------------------------------------------------------------------
// Scratch globals (K^T hi/lo in [h][d][s]; V hi/lo in [h][s][d])
// ---------------------------------------------------------------------------
__device__ __align__(16) __nv_bfloat16 g_khiT[(size_t)H * DH * SEQ];
__device__ __align__(16) __nv_bfloat16 g_kloT[(size_t)H * DH * SEQ];
__device__ __align__(16) __nv_bfloat16 g_vhi[(size_t)H * SEQ * DH];
__device__ __align__(16) __nv_bfloat16 g_vlo[(size_t)H * SEQ * DH];

__device__ __forceinline__ uint32_t cvtpack(float a, float b) {
    uint32_t r;
    asm("cvt.rn.bf16x2.f32 %0, %2, %1;" : "=r"(r) : "f"(a), "f"(b));
    return r;
}
__device__ __forceinline__ float2 unpack_bf(uint32_t u) {
    __nv_bfloat162 t;
    *reinterpret_cast<uint32_t*>(&t) = u;
    return __bfloat1622float2(t);
}
__device__ __forceinline__ float ex2f(float x) {
    float r;
    asm("ex2.approx.f32 %0, %1;" : "=f"(r) : "f"(x));
    return r;
}
__device__ __forceinline__ uint32_t smem_u32(const void* p) {
    uint32_t a;
    asm("{ .reg .u64 t; cvta.to.shared.u64 t, %1; cvt.u32.u64 %0, t; }" : "=r"(a) : "l"(p));
    return a;
}
__device__ __forceinline__ void ldmx4t(uint32_t& r0, uint32_t& r1, uint32_t& r2, uint32_t& r3,
                                       uint32_t addr) {
    asm volatile("ldmatrix.sync.aligned.m8n8.x4.trans.shared.b16 {%0,%1,%2,%3}, [%4];"
                 : "=r"(r0), "=r"(r1), "=r"(r2), "=r"(r3) : "r"(addr));
}
__device__ __forceinline__ void mma_bf16(float* c, const uint32_t* a, uint32_t b0, uint32_t b1) {
    asm volatile("mma.sync.aligned.m16n8k16.row.col.f32.bf16.bf16.f32 "
                 "{%0,%1,%2,%3}, {%4,%5,%6,%7}, {%8,%9}, {%0,%1,%2,%3};"
                 : "+f"(c[0]), "+f"(c[1]), "+f"(c[2]), "+f"(c[3])
                 : "r"(a[0]), "r"(a[1]), "r"(a[2]), "r"(a[3]), "r"(b0), "r"(b1));
}
#define CP_ASYNC16(dst, src) do { \
    size_t _g = __cvta_generic_to_global((const void*)(src)); \
    asm volatile("cp.async.cg.shared.global [%0], [%1], 16;" :: "r"(dst), "l"(_g) : "memory"); \
} while (0)
#define CP_COMMIT() asm volatile("cp.async.commit_group;" ::: "memory")
#define CP_WAIT0()  asm volatile("cp.async.wait_group 0;" ::: "memory")
#define CP_WAIT1()  asm volatile("cp.async.wait_group 1;" ::: "memory")

extern __shared__ char sm_dyn[];

// ---------------------------------------------------------------------------
// K quantization via exact 4-level radix select, values register-resident.
// One 256-thread block handles slices (h, d0..d0+3); single coalesced read.
// Outlier semantics identical to jax.lax.top_k (largest; ties -> lowest idx).
// ---------------------------------------------------------------------------
__global__ __launch_bounds__(256) void kquant_kernel(const float* __restrict__ kin) {
    __shared__ int      hist[4][256];
    __shared__ uint32_t pfx[4];
    __shared__ int      kk[4];
    __shared__ int      ntie[4];
    __shared__ int      tlist[4][32];
    __shared__ float    wmaxs[8][4];
    __shared__ float    sgv[4];

    const int b = blockIdx.x;
    const int h = b >> 5;
    const int d0 = (b & 31) * 4;
    const int tid = threadIdx.x;
    const int lane = tid & 31, wid = tid >> 5;

    const float* base = kin + (size_t)h * SEQ * DH + d0;

    // ---- single coalesced load into registers ----
    float4 vals[8];
#pragma unroll
    for (int j = 0; j < 8; ++j)
        vals[j] = *(const float4*)(base + (size_t)(tid + 256 * j) * DH);

    if (tid < 4) { pfx[tid] = 0u; kk[tid] = NOUT; ntie[tid] = 0; }

    // ---- 4 radix levels over register data ----
#pragma unroll
    for (int l = 0; l < 4; ++l) {
        for (int i = tid; i < 1024; i += 256) ((int*)hist)[i] = 0;
        __syncthreads();
        const int sh = 24 - 8 * l;
#pragma unroll
        for (int j = 0; j < 8; ++j) {
            uint32_t uu[4] = {__float_as_uint(vals[j].x) & 0x7fffffffu,
                              __float_as_uint(vals[j].y) & 0x7fffffffu,
                              __float_as_uint(vals[j].z) & 0x7fffffffu,
                              __float_as_uint(vals[j].w) & 0x7fffffffu};
#pragma unroll
            for (int c = 0; c < 4; ++c) {
                bool m = (l == 0) || ((uu[c] >> (sh + 8)) == pfx[c]);
                if (m) {
                    int bin = (uu[c] >> sh) & 0xff;
                    uint32_t am = __activemask();
                    uint32_t mk = __match_any_sync(am, bin);
                    if ((int)(__ffs(mk) - 1) == lane)
                        atomicAdd(&hist[c][bin], __popc(mk));
                }
            }
        }
        __syncthreads();
        if (wid < 4) {
            const int c = wid;
            int k = kk[c];
            int b0 = 255 - 8 * lane;
            int s = 0;
#pragma unroll
            for (int t = 0; t < 8; ++t) s += hist[c][b0 - t];
            int incl = s;
#pragma unroll
            for (int o = 1; o < 32; o <<= 1) {
                int x = __shfl_up_sync(0xffffffffu, incl, o);
                if (lane >= o) incl += x;
            }
            uint32_t ball = __ballot_sync(0xffffffffu, incl >= k);
            int L = __ffs(ball) - 1;
            if (lane == L) {
                int cum = incl - s;
                for (int t = 0; t < 8; ++t) {
                    int bb = b0 - t;
                    int hcnt = hist[c][bb];
                    cum += hcnt;
                    if (cum >= k) {
                        kk[c] = k - (cum - hcnt);
                        pfx[c] = (pfx[c] << 8) | (uint32_t)bb;
                        break;
                    }
                }
            }
        }
        __syncthreads();
    }

    // ---- tie indices (elements exactly equal to threshold T) ----
#pragma unroll
    for (int j = 0; j < 8; ++j) {
        int r = tid + 256 * j;
        uint32_t uu[4] = {__float_as_uint(vals[j].x) & 0x7fffffffu,
                          __float_as_uint(vals[j].y) & 0x7fffffffu,
                          __float_as_uint(vals[j].z) & 0x7fffffffu,
                          __float_as_uint(vals[j].w) & 0x7fffffffu};
#pragma unroll
        for (int c = 0; c < 4; ++c) {
            if (uu[c] == pfx[c]) {
                int p = atomicAdd(&ntie[c], 1);
                if (p < 32) tlist[c][p] = r;
            }
        }
    }
    __syncthreads();

    // ---- outlier mask + dense max ----
    uint32_t omask = 0;
    float lmax[4] = {0.0f, 0.0f, 0.0f, 0.0f};
#pragma unroll
    for (int j = 0; j < 8; ++j) {
        int r = tid + 256 * j;
        uint32_t uu[4] = {__float_as_uint(vals[j].x) & 0x7fffffffu,
                          __float_as_uint(vals[j].y) & 0x7fffffffu,
                          __float_as_uint(vals[j].z) & 0x7fffffffu,
                          __float_as_uint(vals[j].w) & 0x7fffffffu};
#pragma unroll
        for (int c = 0; c < 4; ++c) {
            bool out;
            uint32_t T = pfx[c];
            if (uu[c] > T) out = true;
            else if (uu[c] == T) {
                int nt = min(ntie[c], 32);
                int rank = 0;
                for (int t = 0; t < nt; ++t) rank += (tlist[c][t] < r);
                out = (rank < kk[c]);
            } else out = false;
            if (out) omask |= 1u << (j * 4 + c);
            else lmax[c] = fmaxf(lmax[c], __uint_as_float(uu[c]));
        }
    }
#pragma unroll
    for (int c = 0; c < 4; ++c) {
#pragma unroll
        for (int o = 16; o > 0; o >>= 1)
            lmax[c] = fmaxf(lmax[c], __shfl_xor_sync(0xffffffffu, lmax[c], o));
    }
    if (lane == 0) {
#pragma unroll
        for (int c = 0; c < 4; ++c) wmaxs[wid][c] = lmax[c];
    }
    __syncthreads();
    if (tid < 4) {
        float m = wmaxs[0][tid];
#pragma unroll
        for (int wjj = 1; wjj < 8; ++wjj) m = fmaxf(m, wmaxs[wjj][tid]);
        sgv[tid] = m;
    }
    __syncthreads();

    float sc[4];
#pragma unroll
    for (int c = 0; c < 4; ++c) sc[c] = fmaxf(sgv[c], 1e-6f) / QMAXF;

    // ---- quantize + split + coalesced store ----
#pragma unroll
    for (int j = 0; j < 8; ++j) {
        int r = tid + 256 * j;
        float vv[4] = {vals[j].x, vals[j].y, vals[j].z, vals[j].w};
#pragma unroll
        for (int c = 0; c < 4; ++c) {
            float v = vv[c];
            float o;
            if (omask & (1u << (j * 4 + c))) o = v;
            else {
                float qq = rintf(__fdiv_rn(v, sc[c]));
                qq = fminf(fmaxf(qq, -QMAXF), QMAXF);
                o = qq * sc[c];
            }
            __nv_bfloat16 hi = __float2bfloat16_rn(o);
            __nv_bfloat16 lo = __float2bfloat16_rn(o - __bfloat162float(hi));
            size_t oidx = ((size_t)h * DH + d0 + c) * SEQ + r;
            g_khiT[oidx] = hi;
            g_kloT[oidx] = lo;
        }
    }
}

// ---------------------------------------------------------------------------
// V quantization + bf16 split, fused. One 128-thread block per (h, s) row.
// ---------------------------------------------------------------------------
__global__ __launch_bounds__(128) void vquant_kernel(const float* __restrict__ vin) {
    const int row = blockIdx.x;
    const int tid = threadIdx.x;

    float v = vin[(size_t)row * DH + tid];
    float a = fabsf(v);

    __shared__ float sab[DH];
    sab[tid] = a;
    __syncthreads();

    int rank = 0;
#pragma unroll 8
    for (int j = 0; j < DH; ++j) {
        float b = sab[j];
        rank += (b > a) || (b == a && j < tid);
    }
    const bool outl = (rank < NOUT);

    float da = outl ? 0.0f : a;
#pragma unroll
    for (int o = 16; o > 0; o >>= 1) da = fmaxf(da, __shfl_xor_sync(0xffffffffu, da, o));
    __shared__ float wmax[4];
    if ((tid & 31) == 0) wmax[tid >> 5] = da;
    __syncthreads();
    float mx = fmaxf(fmaxf(wmax[0], wmax[1]), fmaxf(wmax[2], wmax[3]));
    float scale = fmaxf(mx, 1e-6f) / QMAXF;

    float o;
    if (outl) o = v;
    else {
        float qq = rintf(__fdiv_rn(v, scale));
        qq = fminf(fmaxf(qq, -QMAXF), QMAXF);
        o = qq * scale;
    }
    __nv_bfloat16 hi = __float2bfloat16_rn(o);
    __nv_bfloat16 lo = __float2bfloat16_rn(o - __bfloat162float(hi));
    g_vhi[(size_t)row * DH + tid] = hi;
    g_vlo[(size_t)row * DH + tid] = lo;
}

// ---------------------------------------------------------------------------
// FA2 split-bf16 mma.sync flash attention; B operands via ldmatrix.x4.trans.
// Softmax in exp2 domain; O-rescale skipped when warp-uniformly corr == 1.
// Block = 128 threads, BM=64, BN=64, D=128, 71680 B smem, 3 blocks/SM,
// in-place cp.async phase pipeline.
// ---------------------------------------------------------------------------
#define SKT_HI 0
#define SKT_LO 18432
#define SV_HI  36864
#define SV_LO  54272
#define ATTN_SMEM 71680
#define KTSTR 144
#define VSTR  272

__global__ __launch_bounds__(128, 3)
void attn_mma_kernel(const float* __restrict__ qin, float* __restrict__ out) {
    const uint32_t sb = smem_u32(sm_dyn);
    const int tid  = threadIdx.x;
    const int lane = tid & 31;
    const int w    = tid >> 5;
    const int bx = blockIdx.x;
    const int h  = bx & 31;
    const int qt = 31 - (bx >> 5);          // heavy tiles first
    const int qglob = qt * 64;

    const int quad = lane >> 2;
    const int qtr  = lane & 3;
    const int r0 = w * 16 + quad;
    const int rowg0 = qglob + r0;
    const int rowg1 = rowg0 + 8;

    const __nv_bfloat16* khi_h = g_khiT + (size_t)h * DH * SEQ;  // [d][s]
    const __nv_bfloat16* klo_h = g_kloT + (size_t)h * DH * SEQ;
    const __nv_bfloat16* vhi_h = g_vhi + (size_t)h * SEQ * DH;   // [s][d]
    const __nv_bfloat16* vlo_h = g_vlo + (size_t)h * SEQ * DH;

    auto issue_k = [&](int kt) {
        const __nv_bfloat16* kb0 = khi_h + (size_t)kt * 64;
        const __nv_bfloat16* kb1 = klo_h + (size_t)kt * 64;
#pragma unroll
        for (int i = tid; i < 1024; i += 128) {
            int r = i >> 3, c = i & 7;
            uint32_t sa = r * KTSTR + c * 16;
            CP_ASYNC16(sb + SKT_HI + sa, (const uint4*)(kb0 + (size_t)r * SEQ) + c);
            CP_ASYNC16(sb + SKT_LO + sa, (const uint4*)(kb1 + (size_t)r * SEQ) + c);
        }
    };
    auto issue_v = [&](int kt) {
        const uint4* vb0 = (const uint4*)(vhi_h + (size_t)kt * 64 * DH);
        const uint4* vb1 = (const uint4*)(vlo_h + (size_t)kt * 64 * DH);
#pragma unroll
        for (int i = tid; i < 1024; i += 128) {
            int r = i >> 4, c = i & 15;
            uint32_t sa = r * VSTR + c * 16;
            CP_ASYNC16(sb + SV_HI + sa, vb0 + r * 16 + c);
            CP_ASYNC16(sb + SV_LO + sa, vb1 + r * 16 + c);
        }
    };

    issue_k(0);
    CP_COMMIT();

    // ---- stage Q (scaled by 1/sqrt(d)*log2e) fp32, build A-fragments ----
    float* sQf = (float*)(sm_dyn + SV_HI);
    {
        const float sms = 0.12751791677269355f;
        const float4* qbase = (const float4*)(qin + ((size_t)h * SEQ + qglob) * DH);
        for (int i = tid; i < 64 * 32; i += 128) {
            int r = i >> 5, c = i & 31;
            float4 v = qbase[r * 32 + c];
            v.x *= sms; v.y *= sms; v.z *= sms; v.w *= sms;
            *(float4*)&sQf[r * 132 + c * 4] = v;
        }
    }
    __syncthreads();

    uint32_t qhi[8][4], qlo[8][4];
    {
        const float* s0 = &sQf[r0 * 132];
        const float* s1 = &sQf[(r0 + 8) * 132];
#pragma unroll
        for (int kf = 0; kf < 8; ++kf) {
            int k0 = kf * 16 + 2 * qtr;
            float e[4][2] = {{s0[k0], s0[k0 + 1]}, {s1[k0], s1[k0 + 1]},
                             {s0[k0 + 8], s0[k0 + 9]}, {s1[k0 + 8], s1[k0 + 9]}};
#pragma unroll
            for (int j = 0; j < 4; ++j) {
                uint32_t hp = cvtpack(e[j][0], e[j][1]);
                float2 hf = unpack_bf(hp);
                qhi[kf][j] = hp;
                qlo[kf][j] = cvtpack(e[j][0] - hf.x, e[j][1] - hf.y);
            }
        }
    }
    __syncthreads();

    const uint32_t kmt_h = sb + SKT_HI + lane * KTSTR;
    const uint32_t kmt_l = sb + SKT_LO + lane * KTSTR;
    const uint32_t vmt_h = sb + SV_HI + lane * VSTR;
    const uint32_t vmt_l = sb + SV_LO + lane * VSTR;

    float O[16][4];
#pragma unroll
    for (int i = 0; i < 16; ++i)
#pragma unroll
        for (int j = 0; j < 4; ++j) O[i][j] = 0.0f;
    float m0 = -INFINITY, m1 = -INFINITY, l0 = 0.0f, l1 = 0.0f;

    for (int kt = 0; kt <= qt; ++kt) {
        issue_v(kt);
        CP_COMMIT();
        CP_WAIT1();
        __syncthreads();

        float Sc[8][4];
#pragma unroll
        for (int nf = 0; nf < 8; ++nf) {
            Sc[nf][0] = Sc[nf][1] = Sc[nf][2] = Sc[nf][3] = 0.0f;
            uint32_t nof = nf * 16;
#pragma unroll
            for (int kf2 = 0; kf2 < 4; ++kf2) {
                uint32_t koff = kf2 * 32 * KTSTR;
                uint32_t h0, h1, h2, h3, lo0, lo1, lo2, lo3;
                ldmx4t(h0, h1, h2, h3, kmt_h + koff + nof);
                ldmx4t(lo0, lo1, lo2, lo3, kmt_l + koff + nof);
                mma_bf16(Sc[nf], qhi[2 * kf2], h0, h1);
                mma_bf16(Sc[nf], qhi[2 * kf2], lo0, lo1);
                mma_bf16(Sc[nf], qlo[2 * kf2], h0, h1);
                mma_bf16(Sc[nf], qhi[2 * kf2 + 1], h2, h3);
                mma_bf16(Sc[nf], qhi[2 * kf2 + 1], lo2, lo3);
                mma_bf16(Sc[nf], qlo[2 * kf2 + 1], h2, h3);
            }
        }

        CP_WAIT0();
        __syncthreads();

        if (kt < qt) {
            issue_k(kt + 1);
            CP_COMMIT();
        }

        if (kt == qt) {
            int cb = kt * 64 + 2 * qtr;
#pragma unroll
            for (int nf = 0; nf < 8; ++nf) {
                int c0 = cb + nf * 8, c1 = c0 + 1;
                if (c0 > rowg0) Sc[nf][0] = -1e30f;
                if (c1 > rowg0) Sc[nf][1] = -1e30f;
                if (c0 > rowg1) Sc[nf][2] = -1e30f;
                if (c1 > rowg1) Sc[nf][3] = -1e30f;
            }
        }

        float t0 = -INFINITY, t1 = -INFINITY;
#pragma unroll
        for (int nf = 0; nf < 8; ++nf) {
            t0 = fmaxf(t0, fmaxf(Sc[nf][0], Sc[nf][1]));
            t1 = fmaxf(t1, fmaxf(Sc[nf][2], Sc[nf][3]));
        }
        t0 = fmaxf(t0, __shfl_xor_sync(0xffffffffu, t0, 1));
        t0 = fmaxf(t0, __shfl_xor_sync(0xffffffffu, t0, 2));
        t1 = fmaxf(t1, __shfl_xor_sync(0xffffffffu, t1, 1));
        t1 = fmaxf(t1, __shfl_xor_sync(0xffffffffu, t1, 2));
        float n0 = fmaxf(m0, t0), n1 = fmaxf(m1, t1);
        const bool nochange = (n0 == m0) && (n1 == m1);
        const bool skip = __all_sync(0xffffffffu, nochange);

        float rs0 = 0.0f, rs1 = 0.0f;
#pragma unroll
        for (int nf = 0; nf < 8; ++nf) {
            Sc[nf][0] = ex2f(Sc[nf][0] - n0);
            Sc[nf][1] = ex2f(Sc[nf][1] - n0);
            Sc[nf][2] = ex2f(Sc[nf][2] - n1);
            Sc[nf][3] = ex2f(Sc[nf][3] - n1);
            rs0 += Sc[nf][0] + Sc[nf][1];
            rs1 += Sc[nf][2] + Sc[nf][3];
        }
        rs0 += __shfl_xor_sync(0xffffffffu, rs0, 1);
        rs0 += __shfl_xor_sync(0xffffffffu, rs0, 2);
        rs1 += __shfl_xor_sync(0xffffffffu, rs1, 1);
        rs1 += __shfl_xor_sync(0xffffffffu, rs1, 2);

        if (skip) {
            l0 += rs0;
            l1 += rs1;
        } else {
            float c0 = ex2f(m0 - n0), c1 = ex2f(m1 - n1);
            l0 = l0 * c0 + rs0;
            l1 = l1 * c1 + rs1;
#pragma unroll
            for (int i = 0; i < 16; ++i) {
                O[i][0] *= c0; O[i][1] *= c0;
                O[i][2] *= c1; O[i][3] *= c1;
            }
        }
        m0 = n0; m1 = n1;

        uint32_t phi[4][4], plo[4][4];
#pragma unroll
        for (int kv = 0; kv < 4; ++kv) {
            const float* e0 = Sc[2 * kv];
            const float* e1 = Sc[2 * kv + 1];
            float src[4][2] = {{e0[0], e0[1]}, {e0[2], e0[3]}, {e1[0], e1[1]}, {e1[2], e1[3]}};
#pragma unroll
            for (int j = 0; j < 4; ++j) {
                uint32_t hp = cvtpack(src[j][0], src[j][1]);
                float2 hf = unpack_bf(hp);
                phi[kv][j] = hp;
                plo[kv][j] = cvtpack(src[j][0] - hf.x, src[j][1] - hf.y);
            }
        }

#pragma unroll
        for (int nf = 0; nf < 16; ++nf) {
            uint32_t nof = nf * 16;
#pragma unroll
            for (int kv2 = 0; kv2 < 2; ++kv2) {
                uint32_t koff = kv2 * 32 * VSTR;
                uint32_t h0, h1, h2, h3, lo0, lo1, lo2, lo3;
                ldmx4t(h0, h1, h2, h3, vmt_h + koff + nof);
                ldmx4t(lo0, lo1, lo2, lo3, vmt_l + koff + nof);
                mma_bf16(O[nf], phi[2 * kv2], h0, h1);
                mma_bf16(O[nf], phi[2 * kv2], lo0, lo1);
                mma_bf16(O[nf], plo[2 * kv2], h0, h1);
                mma_bf16(O[nf], phi[2 * kv2 + 1], h2, h3);
                mma_bf16(O[nf], phi[2 * kv2 + 1], lo2, lo3);
                mma_bf16(O[nf], plo[2 * kv2 + 1], h2, h3);
            }
        }
        __syncthreads();
    }

    const float i0 = 1.0f / l0, i1 = 1.0f / l1;
    float* ob0 = out + ((size_t)h * SEQ + rowg0) * DH + 2 * qtr;
    float* ob1 = out + ((size_t)h * SEQ + rowg1) * DH + 2 * qtr;
#pragma unroll
    for (int nf = 0; nf < 16; ++nf) {
        float2 a; a.x = O[nf][0] * i0; a.y = O[nf][1] * i0;
        float2 b; b.x = O[nf][2] * i1; b.y = O[nf][3] * i1;
        *(float2*)(ob0 + nf * 8) = a;
        *(float2*)(ob1 + nf * 8) = b;
    }
}

// ---------------------------------------------------------------------------
extern "C" void kernel_launch(void* const* d_in, const int* in_sizes, int n_in,
                              void* d_out, int out_size) {
    const float* q = (const float*)d_in[0];
    const float* k = (const float*)d_in[1];
    const float* v = (const float*)d_in[2];
    float* out = (float*)d_out;

    kquant_kernel<<<H * 32, 256>>>(k);
    vquant_kernel<<<H * SEQ, 128>>>(v);

    cudaFuncSetAttribute(attn_mma_kernel, cudaFuncAttributeMaxDynamicSharedMemorySize, ATTN_SMEM);
    attn_mma_kernel<<<H * 32, 128, ATTN_SMEM>>>(q, out);
}

// round 13
// speedup vs baseline: 1.6942x; 1.6942x over previous
#include <cuda_runtime.h>
#include <cuda_bf16.h>
#include <math.h>
#include <stdint.h>

#define H   32
#define SEQ 2048
#define DH  128
#define NOUT 16
#define QMAXF 7.0f

// ---------------------------------------------------------------------------
// Scratch globals (K^T hi/lo in [h][d][s]; V hi/lo in [h][s][d])
// ---------------------------------------------------------------------------
__device__ __align__(16) __nv_bfloat16 g_khiT[(size_t)H * DH * SEQ];
__device__ __align__(16) __nv_bfloat16 g_kloT[(size_t)H * DH * SEQ];
__device__ __align__(16) __nv_bfloat16 g_vhi[(size_t)H * SEQ * DH];
__device__ __align__(16) __nv_bfloat16 g_vlo[(size_t)H * SEQ * DH];

__device__ __forceinline__ uint32_t cvtpack(float a, float b) {
    uint32_t r;
    asm("cvt.rn.bf16x2.f32 %0, %2, %1;" : "=r"(r) : "f"(a), "f"(b));
    return r;
}
__device__ __forceinline__ float2 unpack_bf(uint32_t u) {
    __nv_bfloat162 t;
    *reinterpret_cast<uint32_t*>(&t) = u;
    return __bfloat1622float2(t);
}
__device__ __forceinline__ float ex2f(float x) {
    float r;
    asm("ex2.approx.f32 %0, %1;" : "=f"(r) : "f"(x));
    return r;
}
__device__ __forceinline__ uint32_t smem_u32(const void* p) {
    uint32_t a;
    asm("{ .reg .u64 t; cvta.to.shared.u64 t, %1; cvt.u32.u64 %0, t; }" : "=r"(a) : "l"(p));
    return a;
}
__device__ __forceinline__ void ldmx4t(uint32_t& r0, uint32_t& r1, uint32_t& r2, uint32_t& r3,
                                       uint32_t addr) {
    asm volatile("ldmatrix.sync.aligned.m8n8.x4.trans.shared.b16 {%0,%1,%2,%3}, [%4];"
                 : "=r"(r0), "=r"(r1), "=r"(r2), "=r"(r3) : "r"(addr));
}
__device__ __forceinline__ void mma_bf16(float* c, const uint32_t* a, uint32_t b0, uint32_t b1) {
    asm volatile("mma.sync.aligned.m16n8k16.row.col.f32.bf16.bf16.f32 "
                 "{%0,%1,%2,%3}, {%4,%5,%6,%7}, {%8,%9}, {%0,%1,%2,%3};"
                 : "+f"(c[0]), "+f"(c[1]), "+f"(c[2]), "+f"(c[3])
                 : "r"(a[0]), "r"(a[1]), "r"(a[2]), "r"(a[3]), "r"(b0), "r"(b1));
}
#define CP_ASYNC16(dst, src) do { \
    size_t _g = __cvta_generic_to_global((const void*)(src)); \
    asm volatile("cp.async.cg.shared.global [%0], [%1], 16;" :: "r"(dst), "l"(_g) : "memory"); \
} while (0)
#define CP_COMMIT() asm volatile("cp.async.commit_group;" ::: "memory")
#define CP_WAIT0()  asm volatile("cp.async.wait_group 0;" ::: "memory")
#define CP_WAIT1()  asm volatile("cp.async.wait_group 1;" ::: "memory")
#define GBAR64(id)  asm volatile("bar.sync %0, 64;" :: "r"(id) : "memory")
#define GBAR128(id) asm volatile("bar.sync %0, 128;" :: "r"(id) : "memory")

extern __shared__ char sm_dyn[];

// ---------------------------------------------------------------------------
// Fused prep kernel. Blocks [0,1024): K quantization (R10-proven path:
// values in registers, abs in 32 KB smem, 16 incremental-argmax passes per
// 64-thread group). Blocks [1024, 1024+32768): V quantization, 2 rows per
// block (128 threads per row, named barriers 5/6).
// ---------------------------------------------------------------------------
#define PREP_SMEM 32768
#define KQ_BLOCKS (H * 32)                 // 1024
#define VQ_BLOCKS (H * SEQ / 2)            // 32768

__global__ __launch_bounds__(256, 4) void prep_kernel(const float* __restrict__ kin,
                                                      const float* __restrict__ vin) {
    const int bid = blockIdx.x;
    const int tid = threadIdx.x;

    if (bid < KQ_BLOCKS) {
        // ================= K quantization (R10 path, verbatim) =============
        float* sabs = (float*)sm_dyn;             // [4][2048]; flagged -> -1
        __shared__ float swv[8];
        __shared__ int   swi[8];
        __shared__ int   sgi[4];
        __shared__ float sgv[4];

        const int h = bid >> 5;
        const int d0 = (bid & 31) * 4;
        const int lane = tid & 31, wid = tid >> 5;
        const int g = tid >> 6;               // slice group 0..3
        const int l = tid & 63;               // lane within group

        const float* base = kin + (size_t)h * SEQ * DH + d0;
        float4 vals[8];
#pragma unroll
        for (int j = 0; j < 8; ++j) {
            int r = tid + 256 * j;
            float4 v = *(const float4*)(base + (size_t)r * DH);
            vals[j] = v;
            sabs[0 * SEQ + r] = fabsf(v.x);
            sabs[1 * SEQ + r] = fabsf(v.y);
            sabs[2 * SEQ + r] = fabsf(v.z);
            sabs[3 * SEQ + r] = fabsf(v.w);
        }
        __syncthreads();

        const float* gabs = sabs + g * SEQ;
        float amax = -1.0f; int aidx = 0;
#pragma unroll
        for (int j = 0; j < 32; ++j) {
            int i = l + 64 * j;
            float a = gabs[i];
            if (a > amax) { amax = a; aidx = i; }
        }

        for (int it = 0; it < NOUT; ++it) {
            float bv = amax; int bi = aidx;
#pragma unroll
            for (int o = 16; o > 0; o >>= 1) {
                float ov = __shfl_xor_sync(0xffffffffu, bv, o);
                int   oi = __shfl_xor_sync(0xffffffffu, bi, o);
                if (ov > bv || (ov == bv && oi < bi)) { bv = ov; bi = oi; }
            }
            if (lane == 0) { swv[wid] = bv; swi[wid] = bi; }
            GBAR64(g + 1);
            if (l == 0) {
                float v0 = swv[2 * g], v1 = swv[2 * g + 1];
                int   i0 = swi[2 * g], i1 = swi[2 * g + 1];
                sgi[g] = (v1 > v0 || (v1 == v0 && i1 < i0)) ? i1 : i0;
            }
            GBAR64(g + 1);
            int gw = sgi[g];
            if ((gw & 63) == l) {
                sabs[g * SEQ + gw] = -1.0f;
                amax = -1.0f; aidx = 0;
#pragma unroll
                for (int j = 0; j < 32; ++j) {
                    int i = l + 64 * j;
                    float a = gabs[i];
                    if (a > amax) { amax = a; aidx = i; }
                }
            }
            GBAR64(g + 1);
        }

        {
            float bv = amax;
#pragma unroll
            for (int o = 16; o > 0; o >>= 1) bv = fmaxf(bv, __shfl_xor_sync(0xffffffffu, bv, o));
            if (lane == 0) swv[wid] = bv;
            GBAR64(g + 1);
            if (l == 0) sgv[g] = fmaxf(swv[2 * g], swv[2 * g + 1]);
        }
        __syncthreads();

        float sc[4];
#pragma unroll
        for (int c = 0; c < 4; ++c) sc[c] = fmaxf(sgv[c], 1e-6f) / QMAXF;

#pragma unroll
        for (int j = 0; j < 8; ++j) {
            int r = tid + 256 * j;
            float vv[4] = {vals[j].x, vals[j].y, vals[j].z, vals[j].w};
#pragma unroll
            for (int c = 0; c < 4; ++c) {
                float v = vv[c];
                float o;
                if (sabs[c * SEQ + r] < 0.0f) o = v;      // outlier, exact
                else {
                    float qq = rintf(__fdiv_rn(v, sc[c]));
                    qq = fminf(fmaxf(qq, -QMAXF), QMAXF);
                    o = qq * sc[c];
                }
                __nv_bfloat16 hi = __float2bfloat16_rn(o);
                __nv_bfloat16 lo = __float2bfloat16_rn(o - __bfloat162float(hi));
                size_t oidx = ((size_t)h * DH + d0 + c) * SEQ + r;
                g_khiT[oidx] = hi;
                g_kloT[oidx] = lo;
            }
        }
    } else {
        // ================= V quantization: 2 rows per block ================
        const int vb = bid - KQ_BLOCKS;
        const int sub = tid >> 7;             // 0 or 1 (which row)
        const int tr  = tid & 127;            // thread within row
        const int row = vb * 2 + sub;
        const int barid = 5 + sub;

        float* sab = (float*)sm_dyn + sub * DH;   // 2 x 128 floats
        __shared__ float wmax2[2][4];

        float v = vin[(size_t)row * DH + tr];
        float a = fabsf(v);
        sab[tr] = a;
        GBAR128(barid);

        int rank = 0;
#pragma unroll 8
        for (int j = 0; j < DH; ++j) {
            float b2 = sab[j];
            rank += (b2 > a) || (b2 == a && j < tr);
        }
        const bool outl = (rank < NOUT);

        float da = outl ? 0.0f : a;
#pragma unroll
        for (int o = 16; o > 0; o >>= 1) da = fmaxf(da, __shfl_xor_sync(0xffffffffu, da, o));
        if ((tr & 31) == 0) wmax2[sub][tr >> 5] = da;
        GBAR128(barid);
        float mx = fmaxf(fmaxf(wmax2[sub][0], wmax2[sub][1]),
                         fmaxf(wmax2[sub][2], wmax2[sub][3]));
        float scale = fmaxf(mx, 1e-6f) / QMAXF;

        float o;
        if (outl) o = v;
        else {
            float qq = rintf(__fdiv_rn(v, scale));
            qq = fminf(fmaxf(qq, -QMAXF), QMAXF);
            o = qq * scale;
        }
        __nv_bfloat16 hi = __float2bfloat16_rn(o);
        __nv_bfloat16 lo = __float2bfloat16_rn(o - __bfloat162float(hi));
        g_vhi[(size_t)row * DH + tr] = hi;
        g_vlo[(size_t)row * DH + tr] = lo;
    }
}

// ---------------------------------------------------------------------------
// FA2 split-bf16 mma.sync flash attention (R10-proven, verbatim).
// B operands via ldmatrix.x4.trans; softmax in exp2 domain.
// Block = 128 threads, BM=64, BN=64, D=128, 71680 B smem, 3 blocks/SM,
// in-place cp.async phase pipeline.
// ---------------------------------------------------------------------------
#define SKT_HI 0
#define SKT_LO 18432
#define SV_HI  36864
#define SV_LO  54272
#define ATTN_SMEM 71680
#define KTSTR 144
#define VSTR  272

__global__ __launch_bounds__(128, 3)
void attn_mma_kernel(const float* __restrict__ qin, float* __restrict__ out) {
    const uint32_t sb = smem_u32(sm_dyn);
    const int tid  = threadIdx.x;
    const int lane = tid & 31;
    const int w    = tid >> 5;
    const int bx = blockIdx.x;
    const int h  = bx & 31;
    const int qt = 31 - (bx >> 5);          // heavy tiles first
    const int qglob = qt * 64;

    const int quad = lane >> 2;
    const int qtr  = lane & 3;
    const int r0 = w * 16 + quad;
    const int rowg0 = qglob + r0;
    const int rowg1 = rowg0 + 8;

    const __nv_bfloat16* khi_h = g_khiT + (size_t)h * DH * SEQ;  // [d][s]
    const __nv_bfloat16* klo_h = g_kloT + (size_t)h * DH * SEQ;
    const __nv_bfloat16* vhi_h = g_vhi + (size_t)h * SEQ * DH;   // [s][d]
    const __nv_bfloat16* vlo_h = g_vlo + (size_t)h * SEQ * DH;

    auto issue_k = [&](int kt) {
        const __nv_bfloat16* kb0 = khi_h + (size_t)kt * 64;
        const __nv_bfloat16* kb1 = klo_h + (size_t)kt * 64;
#pragma unroll
        for (int i = tid; i < 1024; i += 128) {
            int r = i >> 3, c = i & 7;
            uint32_t sa = r * KTSTR + c * 16;
            CP_ASYNC16(sb + SKT_HI + sa, (const uint4*)(kb0 + (size_t)r * SEQ) + c);
            CP_ASYNC16(sb + SKT_LO + sa, (const uint4*)(kb1 + (size_t)r * SEQ) + c);
        }
    };
    auto issue_v = [&](int kt) {
        const uint4* vb0 = (const uint4*)(vhi_h + (size_t)kt * 64 * DH);
        const uint4* vb1 = (const uint4*)(vlo_h + (size_t)kt * 64 * DH);
#pragma unroll
        for (int i = tid; i < 1024; i += 128) {
            int r = i >> 4, c = i & 15;
            uint32_t sa = r * VSTR + c * 16;
            CP_ASYNC16(sb + SV_HI + sa, vb0 + r * 16 + c);
            CP_ASYNC16(sb + SV_LO + sa, vb1 + r * 16 + c);
        }
    };

    issue_k(0);
    CP_COMMIT();

    // ---- stage Q (scaled by 1/sqrt(d)*log2e) fp32, build A-fragments ----
    float* sQf = (float*)(sm_dyn + SV_HI);
    {
        const float sms = 0.12751791677269355f;
        const float4* qbase = (const float4*)(qin + ((size_t)h * SEQ + qglob) * DH);
        for (int i = tid; i < 64 * 32; i += 128) {
            int r = i >> 5, c = i & 31;
            float4 v = qbase[r * 32 + c];
            v.x *= sms; v.y *= sms; v.z *= sms; v.w *= sms;
            *(float4*)&sQf[r * 132 + c * 4] = v;
        }
    }
    __syncthreads();

    uint32_t qhi[8][4], qlo[8][4];
    {
        const float* s0 = &sQf[r0 * 132];
        const float* s1 = &sQf[(r0 + 8) * 132];
#pragma unroll
        for (int kf = 0; kf < 8; ++kf) {
            int k0 = kf * 16 + 2 * qtr;
            float e[4][2] = {{s0[k0], s0[k0 + 1]}, {s1[k0], s1[k0 + 1]},
                             {s0[k0 + 8], s0[k0 + 9]}, {s1[k0 + 8], s1[k0 + 9]}};
#pragma unroll
            for (int j = 0; j < 4; ++j) {
                uint32_t hp = cvtpack(e[j][0], e[j][1]);
                float2 hf = unpack_bf(hp);
                qhi[kf][j] = hp;
                qlo[kf][j] = cvtpack(e[j][0] - hf.x, e[j][1] - hf.y);
            }
        }
    }
    __syncthreads();

    const uint32_t kmt_h = sb + SKT_HI + lane * KTSTR;
    const uint32_t kmt_l = sb + SKT_LO + lane * KTSTR;
    const uint32_t vmt_h = sb + SV_HI + lane * VSTR;
    const uint32_t vmt_l = sb + SV_LO + lane * VSTR;

    float O[16][4];
#pragma unroll
    for (int i = 0; i < 16; ++i)
#pragma unroll
        for (int j = 0; j < 4; ++j) O[i][j] = 0.0f;
    float m0 = -INFINITY, m1 = -INFINITY, l0 = 0.0f, l1 = 0.0f;

    for (int kt = 0; kt <= qt; ++kt) {
        issue_v(kt);
        CP_COMMIT();
        CP_WAIT1();
        __syncthreads();

        float Sc[8][4];
#pragma unroll
        for (int nf = 0; nf < 8; ++nf) {
            Sc[nf][0] = Sc[nf][1] = Sc[nf][2] = Sc[nf][3] = 0.0f;
            uint32_t nof = nf * 16;
#pragma unroll
            for (int kf2 = 0; kf2 < 4; ++kf2) {
                uint32_t koff = kf2 * 32 * KTSTR;
                uint32_t h0, h1, h2, h3, lo0, lo1, lo2, lo3;
                ldmx4t(h0, h1, h2, h3, kmt_h + koff + nof);
                ldmx4t(lo0, lo1, lo2, lo3, kmt_l + koff + nof);
                mma_bf16(Sc[nf], qhi[2 * kf2], h0, h1);
                mma_bf16(Sc[nf], qhi[2 * kf2], lo0, lo1);
                mma_bf16(Sc[nf], qlo[2 * kf2], h0, h1);
                mma_bf16(Sc[nf], qhi[2 * kf2 + 1], h2, h3);
                mma_bf16(Sc[nf], qhi[2 * kf2 + 1], lo2, lo3);
                mma_bf16(Sc[nf], qlo[2 * kf2 + 1], h2, h3);
            }
        }

        CP_WAIT0();
        __syncthreads();

        if (kt < qt) {
            issue_k(kt + 1);
            CP_COMMIT();
        }

        if (kt == qt) {
            int cb = kt * 64 + 2 * qtr;
#pragma unroll
            for (int nf = 0; nf < 8; ++nf) {
                int c0 = cb + nf * 8, c1 = c0 + 1;
                if (c0 > rowg0) Sc[nf][0] = -1e30f;
                if (c1 > rowg0) Sc[nf][1] = -1e30f;
                if (c0 > rowg1) Sc[nf][2] = -1e30f;
                if (c1 > rowg1) Sc[nf][3] = -1e30f;
            }
        }

        float t0 = -INFINITY, t1 = -INFINITY;
#pragma unroll
        for (int nf = 0; nf < 8; ++nf) {
            t0 = fmaxf(t0, fmaxf(Sc[nf][0], Sc[nf][1]));
            t1 = fmaxf(t1, fmaxf(Sc[nf][2], Sc[nf][3]));
        }
        t0 = fmaxf(t0, __shfl_xor_sync(0xffffffffu, t0, 1));
        t0 = fmaxf(t0, __shfl_xor_sync(0xffffffffu, t0, 2));
        t1 = fmaxf(t1, __shfl_xor_sync(0xffffffffu, t1, 1));
        t1 = fmaxf(t1, __shfl_xor_sync(0xffffffffu, t1, 2));
        float n0 = fmaxf(m0, t0), n1 = fmaxf(m1, t1);
        float c0 = ex2f(m0 - n0), c1 = ex2f(m1 - n1);
        m0 = n0; m1 = n1;

        float rs0 = 0.0f, rs1 = 0.0f;
#pragma unroll
        for (int nf = 0; nf < 8; ++nf) {
            Sc[nf][0] = ex2f(Sc[nf][0] - n0);
            Sc[nf][1] = ex2f(Sc[nf][1] - n0);
            Sc[nf][2] = ex2f(Sc[nf][2] - n1);
            Sc[nf][3] = ex2f(Sc[nf][3] - n1);
            rs0 += Sc[nf][0] + Sc[nf][1];
            rs1 += Sc[nf][2] + Sc[nf][3];
        }
        rs0 += __shfl_xor_sync(0xffffffffu, rs0, 1);
        rs0 += __shfl_xor_sync(0xffffffffu, rs0, 2);
        rs1 += __shfl_xor_sync(0xffffffffu, rs1, 1);
        rs1 += __shfl_xor_sync(0xffffffffu, rs1, 2);
        l0 = l0 * c0 + rs0;
        l1 = l1 * c1 + rs1;
#pragma unroll
        for (int i = 0; i < 16; ++i) {
            O[i][0] *= c0; O[i][1] *= c0;
            O[i][2] *= c1; O[i][3] *= c1;
        }

        uint32_t phi[4][4], plo[4][4];
#pragma unroll
        for (int kv = 0; kv < 4; ++kv) {
            const float* e0 = Sc[2 * kv];
            const float* e1 = Sc[2 * kv + 1];
            float src[4][2] = {{e0[0], e0[1]}, {e0[2], e0[3]}, {e1[0], e1[1]}, {e1[2], e1[3]}};
#pragma unroll
            for (int j = 0; j < 4; ++j) {
                uint32_t hp = cvtpack(src[j][0], src[j][1]);
                float2 hf = unpack_bf(hp);
                phi[kv][j] = hp;
                plo[kv][j] = cvtpack(src[j][0] - hf.x, src[j][1] - hf.y);
            }
        }

#pragma unroll
        for (int nf = 0; nf < 16; ++nf) {
            uint32_t nof = nf * 16;
#pragma unroll
            for (int kv2 = 0; kv2 < 2; ++kv2) {
                uint32_t koff = kv2 * 32 * VSTR;
                uint32_t h0, h1, h2, h3, lo0, lo1, lo2, lo3;
                ldmx4t(h0, h1, h2, h3, vmt_h + koff + nof);
                ldmx4t(lo0, lo1, lo2, lo3, vmt_l + koff + nof);
                mma_bf16(O[nf], phi[2 * kv2], h0, h1);
                mma_bf16(O[nf], phi[2 * kv2], lo0, lo1);
                mma_bf16(O[nf], plo[2 * kv2], h0, h1);
                mma_bf16(O[nf], phi[2 * kv2 + 1], h2, h3);
                mma_bf16(O[nf], phi[2 * kv2 + 1], lo2, lo3);
                mma_bf16(O[nf], plo[2 * kv2 + 1], h2, h3);
            }
        }
        __syncthreads();
    }

    const float i0 = 1.0f / l0, i1 = 1.0f / l1;
    float* ob0 = out + ((size_t)h * SEQ + rowg0) * DH + 2 * qtr;
    float* ob1 = out + ((size_t)h * SEQ + rowg1) * DH + 2 * qtr;
#pragma unroll
    for (int nf = 0; nf < 16; ++nf) {
        float2 a; a.x = O[nf][0] * i0; a.y = O[nf][1] * i0;
        float2 b; b.x = O[nf][2] * i1; b.y = O[nf][3] * i1;
        *(float2*)(ob0 + nf * 8) = a;
        *(float2*)(ob1 + nf * 8) = b;
    }
}

// ---------------------------------------------------------------------------
extern "C" void kernel_launch(void* const* d_in, const int* in_sizes, int n_in,
                              void* d_out, int out_size) {
    const float* q = (const float*)d_in[0];
    const float* k = (const float*)d_in[1];
    const float* v = (const float*)d_in[2];
    float* out = (float*)d_out;

    cudaFuncSetAttribute(prep_kernel, cudaFuncAttributeMaxDynamicSharedMemorySize, PREP_SMEM);
    prep_kernel<<<KQ_BLOCKS + VQ_BLOCKS, 256, PREP_SMEM>>>(k, v);

    cudaFuncSetAttribute(attn_mma_kernel, cudaFuncAttributeMaxDynamicSharedMemorySize, ATTN_SMEM);
    attn_mma_kernel<<<H * 32, 128, ATTN_SMEM>>>(q, out);
}

// round 14
// speedup vs baseline: 2.0917x; 1.2347x over previous
#include <cuda_runtime.h>
#include <cuda_bf16.h>
#include <math.h>
#include <stdint.h>

#define H   32
#define SEQ 2048
#define DH  128
#define NOUT 16
#define QMAXF 7.0f

// ---------------------------------------------------------------------------
// Scratch globals (K^T hi/lo in [h][d][s]; V hi/lo in [h][s][d])
// ---------------------------------------------------------------------------
__device__ __align__(16) __nv_bfloat16 g_khiT[(size_t)H * DH * SEQ];
__device__ __align__(16) __nv_bfloat16 g_kloT[(size_t)H * DH * SEQ];
__device__ __align__(16) __nv_bfloat16 g_vhi[(size_t)H * SEQ * DH];
__device__ __align__(16) __nv_bfloat16 g_vlo[(size_t)H * SEQ * DH];

__device__ __forceinline__ uint32_t cvtpack(float a, float b) {   // {lo=a, hi=b}
    uint32_t r;
    asm("cvt.rn.bf16x2.f32 %0, %2, %1;" : "=r"(r) : "f"(a), "f"(b));
    return r;
}
__device__ __forceinline__ float2 unpack_bf(uint32_t u) {
    __nv_bfloat162 t;
    *reinterpret_cast<uint32_t*>(&t) = u;
    return __bfloat1622float2(t);
}
__device__ __forceinline__ float ex2f(float x) {
    float r;
    asm("ex2.approx.f32 %0, %1;" : "=f"(r) : "f"(x));
    return r;
}
__device__ __forceinline__ uint32_t smem_u32(const void* p) {
    uint32_t a;
    asm("{ .reg .u64 t; cvta.to.shared.u64 t, %1; cvt.u32.u64 %0, t; }" : "=r"(a) : "l"(p));
    return a;
}
__device__ __forceinline__ void ldmx4t(uint32_t& r0, uint32_t& r1, uint32_t& r2, uint32_t& r3,
                                       uint32_t addr) {
    asm volatile("ldmatrix.sync.aligned.m8n8.x4.trans.shared.b16 {%0,%1,%2,%3}, [%4];"
                 : "=r"(r0), "=r"(r1), "=r"(r2), "=r"(r3) : "r"(addr));
}
__device__ __forceinline__ void mma_bf16(float* c, const uint32_t* a, uint32_t b0, uint32_t b1) {
    asm volatile("mma.sync.aligned.m16n8k16.row.col.f32.bf16.bf16.f32 "
                 "{%0,%1,%2,%3}, {%4,%5,%6,%7}, {%8,%9}, {%0,%1,%2,%3};"
                 : "+f"(c[0]), "+f"(c[1]), "+f"(c[2]), "+f"(c[3])
                 : "r"(a[0]), "r"(a[1]), "r"(a[2]), "r"(a[3]), "r"(b0), "r"(b1));
}
#define CP_ASYNC16(dst, src) do { \
    size_t _g = __cvta_generic_to_global((const void*)(src)); \
    asm volatile("cp.async.cg.shared.global [%0], [%1], 16;" :: "r"(dst), "l"(_g) : "memory"); \
} while (0)
#define CP_COMMIT() asm volatile("cp.async.commit_group;" ::: "memory")
#define CP_WAIT0()  asm volatile("cp.async.wait_group 0;" ::: "memory")
#define CP_WAIT1()  asm volatile("cp.async.wait_group 1;" ::: "memory")
#define GBAR64(id)  asm volatile("bar.sync %0, 64;" :: "r"(id) : "memory")

extern __shared__ char sm_dyn[];

// ---------------------------------------------------------------------------
// K quantization (R10-proven): values in registers, abs in 32 KB smem,
// 16 incremental-argmax passes per 64-thread group. 1024 blocks x 256 thr.
// ---------------------------------------------------------------------------
#define KQ_SMEM 32768

__global__ __launch_bounds__(256, 4) void kquant_kernel(const float* __restrict__ kin) {
    float* sabs = (float*)sm_dyn;             // [4][2048]; flagged -> -1
    __shared__ float swv[8];
    __shared__ int   swi[8];
    __shared__ int   sgi[4];
    __shared__ float sgv[4];

    const int b = blockIdx.x;
    const int h = b >> 5;
    const int d0 = (b & 31) * 4;
    const int tid = threadIdx.x;
    const int lane = tid & 31, wid = tid >> 5;
    const int g = tid >> 6;
    const int l = tid & 63;

    const float* base = kin + (size_t)h * SEQ * DH + d0;
    float4 vals[8];
#pragma unroll
    for (int j = 0; j < 8; ++j) {
        int r = tid + 256 * j;
        float4 v = *(const float4*)(base + (size_t)r * DH);
        vals[j] = v;
        sabs[0 * SEQ + r] = fabsf(v.x);
        sabs[1 * SEQ + r] = fabsf(v.y);
        sabs[2 * SEQ + r] = fabsf(v.z);
        sabs[3 * SEQ + r] = fabsf(v.w);
    }
    __syncthreads();

    const float* gabs = sabs + g * SEQ;
    float amax = -1.0f; int aidx = 0;
#pragma unroll
    for (int j = 0; j < 32; ++j) {
        int i = l + 64 * j;
        float a = gabs[i];
        if (a > amax) { amax = a; aidx = i; }
    }

    for (int it = 0; it < NOUT; ++it) {
        float bv = amax; int bi = aidx;
#pragma unroll
        for (int o = 16; o > 0; o >>= 1) {
            float ov = __shfl_xor_sync(0xffffffffu, bv, o);
            int   oi = __shfl_xor_sync(0xffffffffu, bi, o);
            if (ov > bv || (ov == bv && oi < bi)) { bv = ov; bi = oi; }
        }
        if (lane == 0) { swv[wid] = bv; swi[wid] = bi; }
        GBAR64(g + 1);
        if (l == 0) {
            float v0 = swv[2 * g], v1 = swv[2 * g + 1];
            int   i0 = swi[2 * g], i1 = swi[2 * g + 1];
            sgi[g] = (v1 > v0 || (v1 == v0 && i1 < i0)) ? i1 : i0;
        }
        GBAR64(g + 1);
        int gw = sgi[g];
        if ((gw & 63) == l) {
            sabs[g * SEQ + gw] = -1.0f;
            amax = -1.0f; aidx = 0;
#pragma unroll
            for (int j = 0; j < 32; ++j) {
                int i = l + 64 * j;
                float a = gabs[i];
                if (a > amax) { amax = a; aidx = i; }
            }
        }
        GBAR64(g + 1);
    }

    {
        float bv = amax;
#pragma unroll
        for (int o = 16; o > 0; o >>= 1) bv = fmaxf(bv, __shfl_xor_sync(0xffffffffu, bv, o));
        if (lane == 0) swv[wid] = bv;
        GBAR64(g + 1);
        if (l == 0) sgv[g] = fmaxf(swv[2 * g], swv[2 * g + 1]);
    }
    __syncthreads();

    float sc[4];
#pragma unroll
    for (int c = 0; c < 4; ++c) sc[c] = fmaxf(sgv[c], 1e-6f) / QMAXF;

#pragma unroll
    for (int j = 0; j < 8; ++j) {
        int r = tid + 256 * j;
        float vv[4] = {vals[j].x, vals[j].y, vals[j].z, vals[j].w};
#pragma unroll
        for (int c = 0; c < 4; ++c) {
            float v = vv[c];
            float o;
            if (sabs[c * SEQ + r] < 0.0f) o = v;
            else {
                float qq = rintf(__fdiv_rn(v, sc[c]));
                qq = fminf(fmaxf(qq, -QMAXF), QMAXF);
                o = qq * sc[c];
            }
            __nv_bfloat16 hi = __float2bfloat16_rn(o);
            __nv_bfloat16 lo = __float2bfloat16_rn(o - __bfloat162float(hi));
            size_t oidx = ((size_t)h * DH + d0 + c) * SEQ + r;
            g_khiT[oidx] = hi;
            g_kloT[oidx] = lo;
        }
    }
}

// ---------------------------------------------------------------------------
// V quantization, warp-per-row, register-only. 8192 blocks x 256 threads.
// Lane holds 4 consecutive channels (coalesced float4). Top-16 of |x| by
// 16 extraction rounds (value desc, index asc == jax.lax.top_k).
// ---------------------------------------------------------------------------
__global__ __launch_bounds__(256) void vquant_kernel(const float* __restrict__ vin) {
    const int lane = threadIdx.x & 31;
    const int row = blockIdx.x * 8 + (threadIdx.x >> 5);

    float4 v4 = *(const float4*)(vin + (size_t)row * DH + lane * 4);
    float vv[4] = {v4.x, v4.y, v4.z, v4.w};
    float av[4] = {fabsf(v4.x), fabsf(v4.y), fabsf(v4.z), fabsf(v4.w)};

    uint32_t omask = 0;
#pragma unroll
    for (int it = 0; it < NOUT; ++it) {
        float bv = -1.0f; int bi = 0x7fffffff;
#pragma unroll
        for (int i = 0; i < 4; ++i)
            if (av[i] > bv) { bv = av[i]; bi = lane * 4 + i; }
#pragma unroll
        for (int o = 16; o > 0; o >>= 1) {
            float ov = __shfl_xor_sync(0xffffffffu, bv, o);
            int   oi = __shfl_xor_sync(0xffffffffu, bi, o);
            if (ov > bv || (ov == bv && oi < bi)) { bv = ov; bi = oi; }
        }
        if ((bi >> 2) == lane) {
            int i = bi & 3;
            omask |= 1u << i;
            av[i] = -1.0f;
        }
    }

    float mx = fmaxf(fmaxf(av[0], av[1]), fmaxf(av[2], av[3]));
#pragma unroll
    for (int o = 16; o > 0; o >>= 1)
        mx = fmaxf(mx, __shfl_xor_sync(0xffffffffu, mx, o));
    const float scale = fmaxf(mx, 1e-6f) / QMAXF;

    float oo[4];
#pragma unroll
    for (int i = 0; i < 4; ++i) {
        float v = vv[i];
        if (omask & (1u << i)) oo[i] = v;
        else {
            float qq = rintf(__fdiv_rn(v, scale));
            qq = fminf(fmaxf(qq, -QMAXF), QMAXF);
            oo[i] = qq * scale;
        }
    }

    uint2 hw, lw;
    {
        __nv_bfloat16 h0 = __float2bfloat16_rn(oo[0]);
        __nv_bfloat16 h1 = __float2bfloat16_rn(oo[1]);
        __nv_bfloat16 h2 = __float2bfloat16_rn(oo[2]);
        __nv_bfloat16 h3 = __float2bfloat16_rn(oo[3]);
        __nv_bfloat16 l0 = __float2bfloat16_rn(oo[0] - __bfloat162float(h0));
        __nv_bfloat16 l1 = __float2bfloat16_rn(oo[1] - __bfloat162float(h1));
        __nv_bfloat16 l2 = __float2bfloat16_rn(oo[2] - __bfloat162float(h2));
        __nv_bfloat16 l3 = __float2bfloat16_rn(oo[3] - __bfloat162float(h3));
        hw.x = (uint32_t)__bfloat16_as_ushort(h0) | ((uint32_t)__bfloat16_as_ushort(h1) << 16);
        hw.y = (uint32_t)__bfloat16_as_ushort(h2) | ((uint32_t)__bfloat16_as_ushort(h3) << 16);
        lw.x = (uint32_t)__bfloat16_as_ushort(l0) | ((uint32_t)__bfloat16_as_ushort(l1) << 16);
        lw.y = (uint32_t)__bfloat16_as_ushort(l2) | ((uint32_t)__bfloat16_as_ushort(l3) << 16);
    }
    *(uint2*)(g_vhi + (size_t)row * DH + lane * 4) = hw;
    *(uint2*)(g_vlo + (size_t)row * DH + lane * 4) = lw;
}

// ---------------------------------------------------------------------------
// FA2 split-bf16 mma.sync flash attention (proven, verbatim; 328 us @ R13).
// ---------------------------------------------------------------------------
#define SKT_HI 0
#define SKT_LO 18432
#define SV_HI  36864
#define SV_LO  54272
#define ATTN_SMEM 71680
#define KTSTR 144
#define VSTR  272

__global__ __launch_bounds__(128, 3)
void attn_mma_kernel(const float* __restrict__ qin, float* __restrict__ out) {
    const uint32_t sb = smem_u32(sm_dyn);
    const int tid  = threadIdx.x;
    const int lane = tid & 31;
    const int w    = tid >> 5;
    const int bx = blockIdx.x;
    const int h  = bx & 31;
    const int qt = 31 - (bx >> 5);
    const int qglob = qt * 64;

    const int quad = lane >> 2;
    const int qtr  = lane & 3;
    const int r0 = w * 16 + quad;
    const int rowg0 = qglob + r0;
    const int rowg1 = rowg0 + 8;

    const __nv_bfloat16* khi_h = g_khiT + (size_t)h * DH * SEQ;
    const __nv_bfloat16* klo_h = g_kloT + (size_t)h * DH * SEQ;
    const __nv_bfloat16* vhi_h = g_vhi + (size_t)h * SEQ * DH;
    const __nv_bfloat16* vlo_h = g_vlo + (size_t)h * SEQ * DH;

    auto issue_k = [&](int kt) {
        const __nv_bfloat16* kb0 = khi_h + (size_t)kt * 64;
        const __nv_bfloat16* kb1 = klo_h + (size_t)kt * 64;
#pragma unroll
        for (int i = tid; i < 1024; i += 128) {
            int r = i >> 3, c = i & 7;
            uint32_t sa = r * KTSTR + c * 16;
            CP_ASYNC16(sb + SKT_HI + sa, (const uint4*)(kb0 + (size_t)r * SEQ) + c);
            CP_ASYNC16(sb + SKT_LO + sa, (const uint4*)(kb1 + (size_t)r * SEQ) + c);
        }
    };
    auto issue_v = [&](int kt) {
        const uint4* vb0 = (const uint4*)(vhi_h + (size_t)kt * 64 * DH);
        const uint4* vb1 = (const uint4*)(vlo_h + (size_t)kt * 64 * DH);
#pragma unroll
        for (int i = tid; i < 1024; i += 128) {
            int r = i >> 4, c = i & 15;
            uint32_t sa = r * VSTR + c * 16;
            CP_ASYNC16(sb + SV_HI + sa, vb0 + r * 16 + c);
            CP_ASYNC16(sb + SV_LO + sa, vb1 + r * 16 + c);
        }
    };

    issue_k(0);
    CP_COMMIT();

    float* sQf = (float*)(sm_dyn + SV_HI);
    {
        const float sms = 0.12751791677269355f;   // 1/sqrt(128) * log2(e)
        const float4* qbase = (const float4*)(qin + ((size_t)h * SEQ + qglob) * DH);
        for (int i = tid; i < 64 * 32; i += 128) {
            int r = i >> 5, c = i & 31;
            float4 v = qbase[r * 32 + c];
            v.x *= sms; v.y *= sms; v.z *= sms; v.w *= sms;
            *(float4*)&sQf[r * 132 + c * 4] = v;
        }
    }
    __syncthreads();

    uint32_t qhi[8][4], qlo[8][4];
    {
        const float* s0 = &sQf[r0 * 132];
        const float* s1 = &sQf[(r0 + 8) * 132];
#pragma unroll
        for (int kf = 0; kf < 8; ++kf) {
            int k0 = kf * 16 + 2 * qtr;
            float e[4][2] = {{s0[k0], s0[k0 + 1]}, {s1[k0], s1[k0 + 1]},
                             {s0[k0 + 8], s0[k0 + 9]}, {s1[k0 + 8], s1[k0 + 9]}};
#pragma unroll
            for (int j = 0; j < 4; ++j) {
                uint32_t hp = cvtpack(e[j][0], e[j][1]);
                float2 hf = unpack_bf(hp);
                qhi[kf][j] = hp;
                qlo[kf][j] = cvtpack(e[j][0] - hf.x, e[j][1] - hf.y);
            }
        }
    }
    __syncthreads();

    const uint32_t kmt_h = sb + SKT_HI + lane * KTSTR;
    const uint32_t kmt_l = sb + SKT_LO + lane * KTSTR;
    const uint32_t vmt_h = sb + SV_HI + lane * VSTR;
    const uint32_t vmt_l = sb + SV_LO + lane * VSTR;

    float O[16][4];
#pragma unroll
    for (int i = 0; i < 16; ++i)
#pragma unroll
        for (int j = 0; j < 4; ++j) O[i][j] = 0.0f;
    float m0 = -INFINITY, m1 = -INFINITY, l0 = 0.0f, l1 = 0.0f;

    for (int kt = 0; kt <= qt; ++kt) {
        issue_v(kt);
        CP_COMMIT();
        CP_WAIT1();
        __syncthreads();

        float Sc[8][4];
#pragma unroll
        for (int nf = 0; nf < 8; ++nf) {
            Sc[nf][0] = Sc[nf][1] = Sc[nf][2] = Sc[nf][3] = 0.0f;
            uint32_t nof = nf * 16;
#pragma unroll
            for (int kf2 = 0; kf2 < 4; ++kf2) {
                uint32_t koff = kf2 * 32 * KTSTR;
                uint32_t h0, h1, h2, h3, lo0, lo1, lo2, lo3;
                ldmx4t(h0, h1, h2, h3, kmt_h + koff + nof);
                ldmx4t(lo0, lo1, lo2, lo3, kmt_l + koff + nof);
                mma_bf16(Sc[nf], qhi[2 * kf2], h0, h1);
                mma_bf16(Sc[nf], qhi[2 * kf2], lo0, lo1);
                mma_bf16(Sc[nf], qlo[2 * kf2], h0, h1);
                mma_bf16(Sc[nf], qhi[2 * kf2 + 1], h2, h3);
                mma_bf16(Sc[nf], qhi[2 * kf2 + 1], lo2, lo3);
                mma_bf16(Sc[nf], qlo[2 * kf2 + 1], h2, h3);
            }
        }

        CP_WAIT0();
        __syncthreads();

        if (kt < qt) {
            issue_k(kt + 1);
            CP_COMMIT();
        }

        if (kt == qt) {
            int cb = kt * 64 + 2 * qtr;
#pragma unroll
            for (int nf = 0; nf < 8; ++nf) {
                int c0 = cb + nf * 8, c1 = c0 + 1;
                if (c0 > rowg0) Sc[nf][0] = -1e30f;
                if (c1 > rowg0) Sc[nf][1] = -1e30f;
                if (c0 > rowg1) Sc[nf][2] = -1e30f;
                if (c1 > rowg1) Sc[nf][3] = -1e30f;
            }
        }

        float t0 = -INFINITY, t1 = -INFINITY;
#pragma unroll
        for (int nf = 0; nf < 8; ++nf) {
            t0 = fmaxf(t0, fmaxf(Sc[nf][0], Sc[nf][1]));
            t1 = fmaxf(t1, fmaxf(Sc[nf][2], Sc[nf][3]));
        }
        t0 = fmaxf(t0, __shfl_xor_sync(0xffffffffu, t0, 1));
        t0 = fmaxf(t0, __shfl_xor_sync(0xffffffffu, t0, 2));
        t1 = fmaxf(t1, __shfl_xor_sync(0xffffffffu, t1, 1));
        t1 = fmaxf(t1, __shfl_xor_sync(0xffffffffu, t1, 2));
        float n0 = fmaxf(m0, t0), n1 = fmaxf(m1, t1);
        float c0 = ex2f(m0 - n0), c1 = ex2f(m1 - n1);
        m0 = n0; m1 = n1;

        float rs0 = 0.0f, rs1 = 0.0f;
#pragma unroll
        for (int nf = 0; nf < 8; ++nf) {
            Sc[nf][0] = ex2f(Sc[nf][0] - n0);
            Sc[nf][1] = ex2f(Sc[nf][1] - n0);
            Sc[nf][2] = ex2f(Sc[nf][2] - n1);
            Sc[nf][3] = ex2f(Sc[nf][3] - n1);
            rs0 += Sc[nf][0] + Sc[nf][1];
            rs1 += Sc[nf][2] + Sc[nf][3];
        }
        rs0 += __shfl_xor_sync(0xffffffffu, rs0, 1);
        rs0 += __shfl_xor_sync(0xffffffffu, rs0, 2);
        rs1 += __shfl_xor_sync(0xffffffffu, rs1, 1);
        rs1 += __shfl_xor_sync(0xffffffffu, rs1, 2);
        l0 = l0 * c0 + rs0;
        l1 = l1 * c1 + rs1;
#pragma unroll
        for (int i = 0; i < 16; ++i) {
            O[i][0] *= c0; O[i][1] *= c0;
            O[i][2] *= c1; O[i][3] *= c1;
        }

        uint32_t phi[4][4], plo[4][4];
#pragma unroll
        for (int kv = 0; kv < 4; ++kv) {
            const float* e0 = Sc[2 * kv];
            const float* e1 = Sc[2 * kv + 1];
            float src[4][2] = {{e0[0], e0[1]}, {e0[2], e0[3]}, {e1[0], e1[1]}, {e1[2], e1[3]}};
#pragma unroll
            for (int j = 0; j < 4; ++j) {
                uint32_t hp = cvtpack(src[j][0], src[j][1]);
                float2 hf = unpack_bf(hp);
                phi[kv][j] = hp;
                plo[kv][j] = cvtpack(src[j][0] - hf.x, src[j][1] - hf.y);
            }
        }

#pragma unroll
        for (int nf = 0; nf < 16; ++nf) {
            uint32_t nof = nf * 16;
#pragma unroll
            for (int kv2 = 0; kv2 < 2; ++kv2) {
                uint32_t koff = kv2 * 32 * VSTR;
                uint32_t h0, h1, h2, h3, lo0, lo1, lo2, lo3;
                ldmx4t(h0, h1, h2, h3, vmt_h + koff + nof);
                ldmx4t(lo0, lo1, lo2, lo3, vmt_l + koff + nof);
                mma_bf16(O[nf], phi[2 * kv2], h0, h1);
                mma_bf16(O[nf], phi[2 * kv2], lo0, lo1);
                mma_bf16(O[nf], plo[2 * kv2], h0, h1);
                mma_bf16(O[nf], phi[2 * kv2 + 1], h2, h3);
                mma_bf16(O[nf], phi[2 * kv2 + 1], lo2, lo3);
                mma_bf16(O[nf], plo[2 * kv2 + 1], h2, h3);
            }
        }
        __syncthreads();
    }

    const float i0 = 1.0f / l0, i1 = 1.0f / l1;
    float* ob0 = out + ((size_t)h * SEQ + rowg0) * DH + 2 * qtr;
    float* ob1 = out + ((size_t)h * SEQ + rowg1) * DH + 2 * qtr;
#pragma unroll
    for (int nf = 0; nf < 16; ++nf) {
        float2 a; a.x = O[nf][0] * i0; a.y = O[nf][1] * i0;
        float2 b; b.x = O[nf][2] * i1; b.y = O[nf][3] * i1;
        *(float2*)(ob0 + nf * 8) = a;
        *(float2*)(ob1 + nf * 8) = b;
    }
}

// ---------------------------------------------------------------------------
extern "C" void kernel_launch(void* const* d_in, const int* in_sizes, int n_in,
                              void* d_out, int out_size) {
    const float* q = (const float*)d_in[0];
    const float* k = (const float*)d_in[1];
    const float* v = (const float*)d_in[2];
    float* out = (float*)d_out;

    cudaFuncSetAttribute(kquant_kernel, cudaFuncAttributeMaxDynamicSharedMemorySize, KQ_SMEM);
    kquant_kernel<<<H * 32, 256, KQ_SMEM>>>(k);
    vquant_kernel<<<H * SEQ / 8, 256>>>(v);

    cudaFuncSetAttribute(attn_mma_kernel, cudaFuncAttributeMaxDynamicSharedMemorySize, ATTN_SMEM);
    attn_mma_kernel<<<H * 32, 128, ATTN_SMEM>>>(q, out);
}

// round 15
// speedup vs baseline: 2.1204x; 1.0137x over previous
#include <cuda_runtime.h>
#include <cuda_bf16.h>
#include <math.h>
#include <stdint.h>

#define H   32
#define SEQ 2048
#define DH  128
#define NOUT 16
#define QMAXF 7.0f

// ---------------------------------------------------------------------------
// Scratch globals (K^T hi/lo in [h][d][s]; V hi/lo in [h][s][d])
// ---------------------------------------------------------------------------
__device__ __align__(16) __nv_bfloat16 g_khiT[(size_t)H * DH * SEQ];
__device__ __align__(16) __nv_bfloat16 g_kloT[(size_t)H * DH * SEQ];
__device__ __align__(16) __nv_bfloat16 g_vhi[(size_t)H * SEQ * DH];
__device__ __align__(16) __nv_bfloat16 g_vlo[(size_t)H * SEQ * DH];

__device__ __forceinline__ uint32_t cvtpack(float a, float b) {   // {lo=a, hi=b}
    uint32_t r;
    asm("cvt.rn.bf16x2.f32 %0, %2, %1;" : "=r"(r) : "f"(a), "f"(b));
    return r;
}
__device__ __forceinline__ float2 unpack_bf(uint32_t u) {
    __nv_bfloat162 t;
    *reinterpret_cast<uint32_t*>(&t) = u;
    return __bfloat1622float2(t);
}
__device__ __forceinline__ float ex2f(float x) {
    float r;
    asm("ex2.approx.f32 %0, %1;" : "=f"(r) : "f"(x));
    return r;
}
__device__ __forceinline__ uint32_t smem_u32(const void* p) {
    uint32_t a;
    asm("{ .reg .u64 t; cvta.to.shared.u64 t, %1; cvt.u32.u64 %0, t; }" : "=r"(a) : "l"(p));
    return a;
}
__device__ __forceinline__ void ldmx4t(uint32_t& r0, uint32_t& r1, uint32_t& r2, uint32_t& r3,
                                       uint32_t addr) {
    asm volatile("ldmatrix.sync.aligned.m8n8.x4.trans.shared.b16 {%0,%1,%2,%3}, [%4];"
                 : "=r"(r0), "=r"(r1), "=r"(r2), "=r"(r3) : "r"(addr));
}
__device__ __forceinline__ void mma_bf16(float* c, const uint32_t* a, uint32_t b0, uint32_t b1) {
    asm volatile("mma.sync.aligned.m16n8k16.row.col.f32.bf16.bf16.f32 "
                 "{%0,%1,%2,%3}, {%4,%5,%6,%7}, {%8,%9}, {%0,%1,%2,%3};"
                 : "+f"(c[0]), "+f"(c[1]), "+f"(c[2]), "+f"(c[3])
                 : "r"(a[0]), "r"(a[1]), "r"(a[2]), "r"(a[3]), "r"(b0), "r"(b1));
}
#define CP_ASYNC16(dst, src) do { \
    size_t _g = __cvta_generic_to_global((const void*)(src)); \
    asm volatile("cp.async.cg.shared.global [%0], [%1], 16;" :: "r"(dst), "l"(_g) : "memory"); \
} while (0)
#define CP_COMMIT() asm volatile("cp.async.commit_group;" ::: "memory")
#define CP_WAIT0()  asm volatile("cp.async.wait_group 0;" ::: "memory")
#define CP_WAIT1()  asm volatile("cp.async.wait_group 1;" ::: "memory")
#define GBAR64(id)  asm volatile("bar.sync %0, 64;" :: "r"(id) : "memory")

extern __shared__ char sm_dyn[];

// ---------------------------------------------------------------------------
// Fused prep kernel.
// Blocks [0, 1024):      K quantization (R10-proven path, verbatim).
// Blocks [1024, 9216):   V quantization (R14-proven warp-per-row, verbatim).
// ---------------------------------------------------------------------------
#define PREP_SMEM 32768
#define KQ_BLOCKS (H * 32)            // 1024
#define VQ_BLOCKS (H * SEQ / 8)       // 8192

__global__ __launch_bounds__(256, 4) void prep_kernel(const float* __restrict__ kin,
                                                      const float* __restrict__ vin) {
    const int bid = blockIdx.x;
    const int tid = threadIdx.x;

    if (bid < KQ_BLOCKS) {
        // ===================== K quantization =====================
        float* sabs = (float*)sm_dyn;             // [4][2048]; flagged -> -1
        __shared__ float swv[8];
        __shared__ int   swi[8];
        __shared__ int   sgi[4];
        __shared__ float sgv[4];

        const int h = bid >> 5;
        const int d0 = (bid & 31) * 4;
        const int lane = tid & 31, wid = tid >> 5;
        const int g = tid >> 6;
        const int l = tid & 63;

        const float* base = kin + (size_t)h * SEQ * DH + d0;
        float4 vals[8];
#pragma unroll
        for (int j = 0; j < 8; ++j) {
            int r = tid + 256 * j;
            float4 v = *(const float4*)(base + (size_t)r * DH);
            vals[j] = v;
            sabs[0 * SEQ + r] = fabsf(v.x);
            sabs[1 * SEQ + r] = fabsf(v.y);
            sabs[2 * SEQ + r] = fabsf(v.z);
            sabs[3 * SEQ + r] = fabsf(v.w);
        }
        __syncthreads();

        const float* gabs = sabs + g * SEQ;
        float amax = -1.0f; int aidx = 0;
#pragma unroll
        for (int j = 0; j < 32; ++j) {
            int i = l + 64 * j;
            float a = gabs[i];
            if (a > amax) { amax = a; aidx = i; }
        }

        for (int it = 0; it < NOUT; ++it) {
            float bv = amax; int bi = aidx;
#pragma unroll
            for (int o = 16; o > 0; o >>= 1) {
                float ov = __shfl_xor_sync(0xffffffffu, bv, o);
                int   oi = __shfl_xor_sync(0xffffffffu, bi, o);
                if (ov > bv || (ov == bv && oi < bi)) { bv = ov; bi = oi; }
            }
            if (lane == 0) { swv[wid] = bv; swi[wid] = bi; }
            GBAR64(g + 1);
            if (l == 0) {
                float v0 = swv[2 * g], v1 = swv[2 * g + 1];
                int   i0 = swi[2 * g], i1 = swi[2 * g + 1];
                sgi[g] = (v1 > v0 || (v1 == v0 && i1 < i0)) ? i1 : i0;
            }
            GBAR64(g + 1);
            int gw = sgi[g];
            if ((gw & 63) == l) {
                sabs[g * SEQ + gw] = -1.0f;
                amax = -1.0f; aidx = 0;
#pragma unroll
                for (int j = 0; j < 32; ++j) {
                    int i = l + 64 * j;
                    float a = gabs[i];
                    if (a > amax) { amax = a; aidx = i; }
                }
            }
            GBAR64(g + 1);
        }

        {
            float bv = amax;
#pragma unroll
            for (int o = 16; o > 0; o >>= 1) bv = fmaxf(bv, __shfl_xor_sync(0xffffffffu, bv, o));
            if (lane == 0) swv[wid] = bv;
            GBAR64(g + 1);
            if (l == 0) sgv[g] = fmaxf(swv[2 * g], swv[2 * g + 1]);
        }
        __syncthreads();

        float sc[4];
#pragma unroll
        for (int c = 0; c < 4; ++c) sc[c] = fmaxf(sgv[c], 1e-6f) / QMAXF;

#pragma unroll
        for (int j = 0; j < 8; ++j) {
            int r = tid + 256 * j;
            float vv[4] = {vals[j].x, vals[j].y, vals[j].z, vals[j].w};
#pragma unroll
            for (int c = 0; c < 4; ++c) {
                float v = vv[c];
                float o;
                if (sabs[c * SEQ + r] < 0.0f) o = v;
                else {
                    float qq = rintf(__fdiv_rn(v, sc[c]));
                    qq = fminf(fmaxf(qq, -QMAXF), QMAXF);
                    o = qq * sc[c];
                }
                __nv_bfloat16 hi = __float2bfloat16_rn(o);
                __nv_bfloat16 lo = __float2bfloat16_rn(o - __bfloat162float(hi));
                size_t oidx = ((size_t)h * DH + d0 + c) * SEQ + r;
                g_khiT[oidx] = hi;
                g_kloT[oidx] = lo;
            }
        }
    } else {
        // ===================== V quantization (warp-per-row) =====================
        const int lane = tid & 31;
        const int row = (bid - KQ_BLOCKS) * 8 + (tid >> 5);

        float4 v4 = *(const float4*)(vin + (size_t)row * DH + lane * 4);
        float vv[4] = {v4.x, v4.y, v4.z, v4.w};
        float av[4] = {fabsf(v4.x), fabsf(v4.y), fabsf(v4.z), fabsf(v4.w)};

        uint32_t omask = 0;
#pragma unroll
        for (int it = 0; it < NOUT; ++it) {
            float bv = -1.0f; int bi = 0x7fffffff;
#pragma unroll
            for (int i = 0; i < 4; ++i)
                if (av[i] > bv) { bv = av[i]; bi = lane * 4 + i; }
#pragma unroll
            for (int o = 16; o > 0; o >>= 1) {
                float ov = __shfl_xor_sync(0xffffffffu, bv, o);
                int   oi = __shfl_xor_sync(0xffffffffu, bi, o);
                if (ov > bv || (ov == bv && oi < bi)) { bv = ov; bi = oi; }
            }
            if ((bi >> 2) == lane) {
                int i = bi & 3;
                omask |= 1u << i;
                av[i] = -1.0f;
            }
        }

        float mx = fmaxf(fmaxf(av[0], av[1]), fmaxf(av[2], av[3]));
#pragma unroll
        for (int o = 16; o > 0; o >>= 1)
            mx = fmaxf(mx, __shfl_xor_sync(0xffffffffu, mx, o));
        const float scale = fmaxf(mx, 1e-6f) / QMAXF;

        float oo[4];
#pragma unroll
        for (int i = 0; i < 4; ++i) {
            float v = vv[i];
            if (omask & (1u << i)) oo[i] = v;
            else {
                float qq = rintf(__fdiv_rn(v, scale));
                qq = fminf(fmaxf(qq, -QMAXF), QMAXF);
                oo[i] = qq * scale;
            }
        }

        uint2 hw, lw;
        {
            __nv_bfloat16 h0 = __float2bfloat16_rn(oo[0]);
            __nv_bfloat16 h1 = __float2bfloat16_rn(oo[1]);
            __nv_bfloat16 h2 = __float2bfloat16_rn(oo[2]);
            __nv_bfloat16 h3 = __float2bfloat16_rn(oo[3]);
            __nv_bfloat16 l0 = __float2bfloat16_rn(oo[0] - __bfloat162float(h0));
            __nv_bfloat16 l1 = __float2bfloat16_rn(oo[1] - __bfloat162float(h1));
            __nv_bfloat16 l2 = __float2bfloat16_rn(oo[2] - __bfloat162float(h2));
            __nv_bfloat16 l3 = __float2bfloat16_rn(oo[3] - __bfloat162float(h3));
            hw.x = (uint32_t)__bfloat16_as_ushort(h0) | ((uint32_t)__bfloat16_as_ushort(h1) << 16);
            hw.y = (uint32_t)__bfloat16_as_ushort(h2) | ((uint32_t)__bfloat16_as_ushort(h3) << 16);
            lw.x = (uint32_t)__bfloat16_as_ushort(l0) | ((uint32_t)__bfloat16_as_ushort(l1) << 16);
            lw.y = (uint32_t)__bfloat16_as_ushort(l2) | ((uint32_t)__bfloat16_as_ushort(l3) << 16);
        }
        *(uint2*)(g_vhi + (size_t)row * DH + lane * 4) = hw;
        *(uint2*)(g_vlo + (size_t)row * DH + lane * 4) = lw;
    }
}

// ---------------------------------------------------------------------------
// FA2 split-bf16 mma.sync flash attention (proven, verbatim; ~328 us).
// ---------------------------------------------------------------------------
#define SKT_HI 0
#define SKT_LO 18432
#define SV_HI  36864
#define SV_LO  54272
#define ATTN_SMEM 71680
#define KTSTR 144
#define VSTR  272

__global__ __launch_bounds__(128, 3)
void attn_mma_kernel(const float* __restrict__ qin, float* __restrict__ out) {
    const uint32_t sb = smem_u32(sm_dyn);
    const int tid  = threadIdx.x;
    const int lane = tid & 31;
    const int w    = tid >> 5;
    const int bx = blockIdx.x;
    const int h  = bx & 31;
    const int qt = 31 - (bx >> 5);
    const int qglob = qt * 64;

    const int quad = lane >> 2;
    const int qtr  = lane & 3;
    const int r0 = w * 16 + quad;
    const int rowg0 = qglob + r0;
    const int rowg1 = rowg0 + 8;

    const __nv_bfloat16* khi_h = g_khiT + (size_t)h * DH * SEQ;
    const __nv_bfloat16* klo_h = g_kloT + (size_t)h * DH * SEQ;
    const __nv_bfloat16* vhi_h = g_vhi + (size_t)h * SEQ * DH;
    const __nv_bfloat16* vlo_h = g_vlo + (size_t)h * SEQ * DH;

    auto issue_k = [&](int kt) {
        const __nv_bfloat16* kb0 = khi_h + (size_t)kt * 64;
        const __nv_bfloat16* kb1 = klo_h + (size_t)kt * 64;
#pragma unroll
        for (int i = tid; i < 1024; i += 128) {
            int r = i >> 3, c = i & 7;
            uint32_t sa = r * KTSTR + c * 16;
            CP_ASYNC16(sb + SKT_HI + sa, (const uint4*)(kb0 + (size_t)r * SEQ) + c);
            CP_ASYNC16(sb + SKT_LO + sa, (const uint4*)(kb1 + (size_t)r * SEQ) + c);
        }
    };
    auto issue_v = [&](int kt) {
        const uint4* vb0 = (const uint4*)(vhi_h + (size_t)kt * 64 * DH);
        const uint4* vb1 = (const uint4*)(vlo_h + (size_t)kt * 64 * DH);
#pragma unroll
        for (int i = tid; i < 1024; i += 128) {
            int r = i >> 4, c = i & 15;
            uint32_t sa = r * VSTR + c * 16;
            CP_ASYNC16(sb + SV_HI + sa, vb0 + r * 16 + c);
            CP_ASYNC16(sb + SV_LO + sa, vb1 + r * 16 + c);
        }
    };

    issue_k(0);
    CP_COMMIT();

    float* sQf = (float*)(sm_dyn + SV_HI);
    {
        const float sms = 0.12751791677269355f;   // 1/sqrt(128) * log2(e)
        const float4* qbase = (const float4*)(qin + ((size_t)h * SEQ + qglob) * DH);
        for (int i = tid; i < 64 * 32; i += 128) {
            int r = i >> 5, c = i & 31;
            float4 v = qbase[r * 32 + c];
            v.x *= sms; v.y *= sms; v.z *= sms; v.w *= sms;
            *(float4*)&sQf[r * 132 + c * 4] = v;
        }
    }
    __syncthreads();

    uint32_t qhi[8][4], qlo[8][4];
    {
        const float* s0 = &sQf[r0 * 132];
        const float* s1 = &sQf[(r0 + 8) * 132];
#pragma unroll
        for (int kf = 0; kf < 8; ++kf) {
            int k0 = kf * 16 + 2 * qtr;
            float e[4][2] = {{s0[k0], s0[k0 + 1]}, {s1[k0], s1[k0 + 1]},
                             {s0[k0 + 8], s0[k0 + 9]}, {s1[k0 + 8], s1[k0 + 9]}};
#pragma unroll
            for (int j = 0; j < 4; ++j) {
                uint32_t hp = cvtpack(e[j][0], e[j][1]);
                float2 hf = unpack_bf(hp);
                qhi[kf][j] = hp;
                qlo[kf][j] = cvtpack(e[j][0] - hf.x, e[j][1] - hf.y);
            }
        }
    }
    __syncthreads();

    const uint32_t kmt_h = sb + SKT_HI + lane * KTSTR;
    const uint32_t kmt_l = sb + SKT_LO + lane * KTSTR;
    const uint32_t vmt_h = sb + SV_HI + lane * VSTR;
    const uint32_t vmt_l = sb + SV_LO + lane * VSTR;

    float O[16][4];
#pragma unroll
    for (int i = 0; i < 16; ++i)
#pragma unroll
        for (int j = 0; j < 4; ++j) O[i][j] = 0.0f;
    float m0 = -INFINITY, m1 = -INFINITY, l0 = 0.0f, l1 = 0.0f;

    for (int kt = 0; kt <= qt; ++kt) {
        issue_v(kt);
        CP_COMMIT();
        CP_WAIT1();
        __syncthreads();

        float Sc[8][4];
#pragma unroll
        for (int nf = 0; nf < 8; ++nf) {
            Sc[nf][0] = Sc[nf][1] = Sc[nf][2] = Sc[nf][3] = 0.0f;
            uint32_t nof = nf * 16;
#pragma unroll
            for (int kf2 = 0; kf2 < 4; ++kf2) {
                uint32_t koff = kf2 * 32 * KTSTR;
                uint32_t h0, h1, h2, h3, lo0, lo1, lo2, lo3;
                ldmx4t(h0, h1, h2, h3, kmt_h + koff + nof);
                ldmx4t(lo0, lo1, lo2, lo3, kmt_l + koff + nof);
                mma_bf16(Sc[nf], qhi[2 * kf2], h0, h1);
                mma_bf16(Sc[nf], qhi[2 * kf2], lo0, lo1);
                mma_bf16(Sc[nf], qlo[2 * kf2], h0, h1);
                mma_bf16(Sc[nf], qhi[2 * kf2 + 1], h2, h3);
                mma_bf16(Sc[nf], qhi[2 * kf2 + 1], lo2, lo3);
                mma_bf16(Sc[nf], qlo[2 * kf2 + 1], h2, h3);
            }
        }

        CP_WAIT0();
        __syncthreads();

        if (kt < qt) {
            issue_k(kt + 1);
            CP_COMMIT();
        }

        if (kt == qt) {
            int cb = kt * 64 + 2 * qtr;
#pragma unroll
            for (int nf = 0; nf < 8; ++nf) {
                int c0 = cb + nf * 8, c1 = c0 + 1;
                if (c0 > rowg0) Sc[nf][0] = -1e30f;
                if (c1 > rowg0) Sc[nf][1] = -1e30f;
                if (c0 > rowg1) Sc[nf][2] = -1e30f;
                if (c1 > rowg1) Sc[nf][3] = -1e30f;
            }
        }

        float t0 = -INFINITY, t1 = -INFINITY;
#pragma unroll
        for (int nf = 0; nf < 8; ++nf) {
            t0 = fmaxf(t0, fmaxf(Sc[nf][0], Sc[nf][1]));
            t1 = fmaxf(t1, fmaxf(Sc[nf][2], Sc[nf][3]));
        }
        t0 = fmaxf(t0, __shfl_xor_sync(0xffffffffu, t0, 1));
        t0 = fmaxf(t0, __shfl_xor_sync(0xffffffffu, t0, 2));
        t1 = fmaxf(t1, __shfl_xor_sync(0xffffffffu, t1, 1));
        t1 = fmaxf(t1, __shfl_xor_sync(0xffffffffu, t1, 2));
        float n0 = fmaxf(m0, t0), n1 = fmaxf(m1, t1);
        float c0 = ex2f(m0 - n0), c1 = ex2f(m1 - n1);
        m0 = n0; m1 = n1;

        float rs0 = 0.0f, rs1 = 0.0f;
#pragma unroll
        for (int nf = 0; nf < 8; ++nf) {
            Sc[nf][0] = ex2f(Sc[nf][0] - n0);
            Sc[nf][1] = ex2f(Sc[nf][1] - n0);
            Sc[nf][2] = ex2f(Sc[nf][2] - n1);
            Sc[nf][3] = ex2f(Sc[nf][3] - n1);
            rs0 += Sc[nf][0] + Sc[nf][1];
            rs1 += Sc[nf][2] + Sc[nf][3];
        }
        rs0 += __shfl_xor_sync(0xffffffffu, rs0, 1);
        rs0 += __shfl_xor_sync(0xffffffffu, rs0, 2);
        rs1 += __shfl_xor_sync(0xffffffffu, rs1, 1);
        rs1 += __shfl_xor_sync(0xffffffffu, rs1, 2);
        l0 = l0 * c0 + rs0;
        l1 = l1 * c1 + rs1;
#pragma unroll
        for (int i = 0; i < 16; ++i) {
            O[i][0] *= c0; O[i][1] *= c0;
            O[i][2] *= c1; O[i][3] *= c1;
        }

        uint32_t phi[4][4], plo[4][4];
#pragma unroll
        for (int kv = 0; kv < 4; ++kv) {
            const float* e0 = Sc[2 * kv];
            const float* e1 = Sc[2 * kv + 1];
            float src[4][2] = {{e0[0], e0[1]}, {e0[2], e0[3]}, {e1[0], e1[1]}, {e1[2], e1[3]}};
#pragma unroll
            for (int j = 0; j < 4; ++j) {
                uint32_t hp = cvtpack(src[j][0], src[j][1]);
                float2 hf = unpack_bf(hp);
                phi[kv][j] = hp;
                plo[kv][j] = cvtpack(src[j][0] - hf.x, src[j][1] - hf.y);
            }
        }

#pragma unroll
        for (int nf = 0; nf < 16; ++nf) {
            uint32_t nof = nf * 16;
#pragma unroll
            for (int kv2 = 0; kv2 < 2; ++kv2) {
                uint32_t koff = kv2 * 32 * VSTR;
                uint32_t h0, h1, h2, h3, lo0, lo1, lo2, lo3;
                ldmx4t(h0, h1, h2, h3, vmt_h + koff + nof);
                ldmx4t(lo0, lo1, lo2, lo3, vmt_l + koff + nof);
                mma_bf16(O[nf], phi[2 * kv2], h0, h1);
                mma_bf16(O[nf], phi[2 * kv2], lo0, lo1);
                mma_bf16(O[nf], plo[2 * kv2], h0, h1);
                mma_bf16(O[nf], phi[2 * kv2 + 1], h2, h3);
                mma_bf16(O[nf], phi[2 * kv2 + 1], lo2, lo3);
                mma_bf16(O[nf], plo[2 * kv2 + 1], h2, h3);
            }
        }
        __syncthreads();
    }

    const float i0 = 1.0f / l0, i1 = 1.0f / l1;
    float* ob0 = out + ((size_t)h * SEQ + rowg0) * DH + 2 * qtr;
    float* ob1 = out + ((size_t)h * SEQ + rowg1) * DH + 2 * qtr;
#pragma unroll
    for (int nf = 0; nf < 16; ++nf) {
        float2 a; a.x = O[nf][0] * i0; a.y = O[nf][1] * i0;
        float2 b; b.x = O[nf][2] * i1; b.y = O[nf][3] * i1;
        *(float2*)(ob0 + nf * 8) = a;
        *(float2*)(ob1 + nf * 8) = b;
    }
}

// ---------------------------------------------------------------------------
extern "C" void kernel_launch(void* const* d_in, const int* in_sizes, int n_in,
                              void* d_out, int out_size) {
    const float* q = (const float*)d_in[0];
    const float* k = (const float*)d_in[1];
    const float* v = (const float*)d_in[2];
    float* out = (float*)d_out;

    cudaFuncSetAttribute(prep_kernel, cudaFuncAttributeMaxDynamicSharedMemorySize, PREP_SMEM);
    prep_kernel<<<KQ_BLOCKS + VQ_BLOCKS, 256, PREP_SMEM>>>(k, v);

    cudaFuncSetAttribute(attn_mma_kernel, cudaFuncAttributeMaxDynamicSharedMemorySize, ATTN_SMEM);
    attn_mma_kernel<<<H * 32, 128, ATTN_SMEM>>>(q, out);
}

// round 16
// speedup vs baseline: 2.1766x; 1.0265x over previous
#include <cuda_runtime.h>
#include <cuda_bf16.h>
#include <math.h>
#include <stdint.h>

#define H   32
#define SEQ 2048
#define DH  128
#define NOUT 16
#define QMAXF 7.0f

// ---------------------------------------------------------------------------
// Scratch globals (K^T hi/lo in [h][d][s]; V hi/lo in [h][s][d])
// ---------------------------------------------------------------------------
__device__ __align__(16) __nv_bfloat16 g_khiT[(size_t)H * DH * SEQ];
__device__ __align__(16) __nv_bfloat16 g_kloT[(size_t)H * DH * SEQ];
__device__ __align__(16) __nv_bfloat16 g_vhi[(size_t)H * SEQ * DH];
__device__ __align__(16) __nv_bfloat16 g_vlo[(size_t)H * SEQ * DH];

__device__ __forceinline__ uint32_t cvtpack(float a, float b) {   // {lo=a, hi=b}
    uint32_t r;
    asm("cvt.rn.bf16x2.f32 %0, %2, %1;" : "=r"(r) : "f"(a), "f"(b));
    return r;
}
__device__ __forceinline__ float2 unpack_bf(uint32_t u) {
    __nv_bfloat162 t;
    *reinterpret_cast<uint32_t*>(&t) = u;
    return __bfloat1622float2(t);
}
__device__ __forceinline__ float ex2f(float x) {
    float r;
    asm("ex2.approx.f32 %0, %1;" : "=f"(r) : "f"(x));
    return r;
}
__device__ __forceinline__ uint32_t smem_u32(const void* p) {
    uint32_t a;
    asm("{ .reg .u64 t; cvta.to.shared.u64 t, %1; cvt.u32.u64 %0, t; }" : "=r"(a) : "l"(p));
    return a;
}
__device__ __forceinline__ void ldmx4t(uint32_t& r0, uint32_t& r1, uint32_t& r2, uint32_t& r3,
                                       uint32_t addr) {
    asm volatile("ldmatrix.sync.aligned.m8n8.x4.trans.shared.b16 {%0,%1,%2,%3}, [%4];"
                 : "=r"(r0), "=r"(r1), "=r"(r2), "=r"(r3) : "r"(addr));
}
__device__ __forceinline__ void mma_bf16(float* c, const uint32_t* a, uint32_t b0, uint32_t b1) {
    asm volatile("mma.sync.aligned.m16n8k16.row.col.f32.bf16.bf16.f32 "
                 "{%0,%1,%2,%3}, {%4,%5,%6,%7}, {%8,%9}, {%0,%1,%2,%3};"
                 : "+f"(c[0]), "+f"(c[1]), "+f"(c[2]), "+f"(c[3])
                 : "r"(a[0]), "r"(a[1]), "r"(a[2]), "r"(a[3]), "r"(b0), "r"(b1));
}
#define CP_ASYNC16(dst, src) do { \
    size_t _g = __cvta_generic_to_global((const void*)(src)); \
    asm volatile("cp.async.cg.shared.global [%0], [%1], 16;" :: "r"(dst), "l"(_g) : "memory"); \
} while (0)
#define CP_COMMIT() asm volatile("cp.async.commit_group;" ::: "memory")
#define CP_WAIT0()  asm volatile("cp.async.wait_group 0;" ::: "memory")
#define CP_WAIT1()  asm volatile("cp.async.wait_group 1;" ::: "memory")
#define GBAR64(id)  asm volatile("bar.sync %0, 64;" :: "r"(id) : "memory")

extern __shared__ char sm_dyn[];

// ---------------------------------------------------------------------------
// Fused prep kernel (R15-proven, verbatim).
// Blocks [0, 1024):      K quantization.
// Blocks [1024, 9216):   V quantization (warp-per-row).
// ---------------------------------------------------------------------------
#define PREP_SMEM 32768
#define KQ_BLOCKS (H * 32)            // 1024
#define VQ_BLOCKS (H * SEQ / 8)       // 8192

__global__ __launch_bounds__(256, 4) void prep_kernel(const float* __restrict__ kin,
                                                      const float* __restrict__ vin) {
    const int bid = blockIdx.x;
    const int tid = threadIdx.x;

    if (bid < KQ_BLOCKS) {
        float* sabs = (float*)sm_dyn;
        __shared__ float swv[8];
        __shared__ int   swi[8];
        __shared__ int   sgi[4];
        __shared__ float sgv[4];

        const int h = bid >> 5;
        const int d0 = (bid & 31) * 4;
        const int lane = tid & 31, wid = tid >> 5;
        const int g = tid >> 6;
        const int l = tid & 63;

        const float* base = kin + (size_t)h * SEQ * DH + d0;
        float4 vals[8];
#pragma unroll
        for (int j = 0; j < 8; ++j) {
            int r = tid + 256 * j;
            float4 v = *(const float4*)(base + (size_t)r * DH);
            vals[j] = v;
            sabs[0 * SEQ + r] = fabsf(v.x);
            sabs[1 * SEQ + r] = fabsf(v.y);
            sabs[2 * SEQ + r] = fabsf(v.z);
            sabs[3 * SEQ + r] = fabsf(v.w);
        }
        __syncthreads();

        const float* gabs = sabs + g * SEQ;
        float amax = -1.0f; int aidx = 0;
#pragma unroll
        for (int j = 0; j < 32; ++j) {
            int i = l + 64 * j;
            float a = gabs[i];
            if (a > amax) { amax = a; aidx = i; }
        }

        for (int it = 0; it < NOUT; ++it) {
            float bv = amax; int bi = aidx;
#pragma unroll
            for (int o = 16; o > 0; o >>= 1) {
                float ov = __shfl_xor_sync(0xffffffffu, bv, o);
                int   oi = __shfl_xor_sync(0xffffffffu, bi, o);
                if (ov > bv || (ov == bv && oi < bi)) { bv = ov; bi = oi; }
            }
            if (lane == 0) { swv[wid] = bv; swi[wid] = bi; }
            GBAR64(g + 1);
            if (l == 0) {
                float v0 = swv[2 * g], v1 = swv[2 * g + 1];
                int   i0 = swi[2 * g], i1 = swi[2 * g + 1];
                sgi[g] = (v1 > v0 || (v1 == v0 && i1 < i0)) ? i1 : i0;
            }
            GBAR64(g + 1);
            int gw = sgi[g];
            if ((gw & 63) == l) {
                sabs[g * SEQ + gw] = -1.0f;
                amax = -1.0f; aidx = 0;
#pragma unroll
                for (int j = 0; j < 32; ++j) {
                    int i = l + 64 * j;
                    float a = gabs[i];
                    if (a > amax) { amax = a; aidx = i; }
                }
            }
            GBAR64(g + 1);
        }

        {
            float bv = amax;
#pragma unroll
            for (int o = 16; o > 0; o >>= 1) bv = fmaxf(bv, __shfl_xor_sync(0xffffffffu, bv, o));
            if (lane == 0) swv[wid] = bv;
            GBAR64(g + 1);
            if (l == 0) sgv[g] = fmaxf(swv[2 * g], swv[2 * g + 1]);
        }
        __syncthreads();

        float sc[4];
#pragma unroll
        for (int c = 0; c < 4; ++c) sc[c] = fmaxf(sgv[c], 1e-6f) / QMAXF;

#pragma unroll
        for (int j = 0; j < 8; ++j) {
            int r = tid + 256 * j;
            float vv[4] = {vals[j].x, vals[j].y, vals[j].z, vals[j].w};
#pragma unroll
            for (int c = 0; c < 4; ++c) {
                float v = vv[c];
                float o;
                if (sabs[c * SEQ + r] < 0.0f) o = v;
                else {
                    float qq = rintf(__fdiv_rn(v, sc[c]));
                    qq = fminf(fmaxf(qq, -QMAXF), QMAXF);
                    o = qq * sc[c];
                }
                __nv_bfloat16 hi = __float2bfloat16_rn(o);
                __nv_bfloat16 lo = __float2bfloat16_rn(o - __bfloat162float(hi));
                size_t oidx = ((size_t)h * DH + d0 + c) * SEQ + r;
                g_khiT[oidx] = hi;
                g_kloT[oidx] = lo;
            }
        }
    } else {
        const int lane = tid & 31;
        const int row = (bid - KQ_BLOCKS) * 8 + (tid >> 5);

        float4 v4 = *(const float4*)(vin + (size_t)row * DH + lane * 4);
        float vv[4] = {v4.x, v4.y, v4.z, v4.w};
        float av[4] = {fabsf(v4.x), fabsf(v4.y), fabsf(v4.z), fabsf(v4.w)};

        uint32_t omask = 0;
#pragma unroll
        for (int it = 0; it < NOUT; ++it) {
            float bv = -1.0f; int bi = 0x7fffffff;
#pragma unroll
            for (int i = 0; i < 4; ++i)
                if (av[i] > bv) { bv = av[i]; bi = lane * 4 + i; }
#pragma unroll
            for (int o = 16; o > 0; o >>= 1) {
                float ov = __shfl_xor_sync(0xffffffffu, bv, o);
                int   oi = __shfl_xor_sync(0xffffffffu, bi, o);
                if (ov > bv || (ov == bv && oi < bi)) { bv = ov; bi = oi; }
            }
            if ((bi >> 2) == lane) {
                int i = bi & 3;
                omask |= 1u << i;
                av[i] = -1.0f;
            }
        }

        float mx = fmaxf(fmaxf(av[0], av[1]), fmaxf(av[2], av[3]));
#pragma unroll
        for (int o = 16; o > 0; o >>= 1)
            mx = fmaxf(mx, __shfl_xor_sync(0xffffffffu, mx, o));
        const float scale = fmaxf(mx, 1e-6f) / QMAXF;

        float oo[4];
#pragma unroll
        for (int i = 0; i < 4; ++i) {
            float v = vv[i];
            if (omask & (1u << i)) oo[i] = v;
            else {
                float qq = rintf(__fdiv_rn(v, scale));
                qq = fminf(fmaxf(qq, -QMAXF), QMAXF);
                oo[i] = qq * scale;
            }
        }

        uint2 hw, lw;
        {
            __nv_bfloat16 h0 = __float2bfloat16_rn(oo[0]);
            __nv_bfloat16 h1 = __float2bfloat16_rn(oo[1]);
            __nv_bfloat16 h2 = __float2bfloat16_rn(oo[2]);
            __nv_bfloat16 h3 = __float2bfloat16_rn(oo[3]);
            __nv_bfloat16 l0 = __float2bfloat16_rn(oo[0] - __bfloat162float(h0));
            __nv_bfloat16 l1 = __float2bfloat16_rn(oo[1] - __bfloat162float(h1));
            __nv_bfloat16 l2 = __float2bfloat16_rn(oo[2] - __bfloat162float(h2));
            __nv_bfloat16 l3 = __float2bfloat16_rn(oo[3] - __bfloat162float(h3));
            hw.x = (uint32_t)__bfloat16_as_ushort(h0) | ((uint32_t)__bfloat16_as_ushort(h1) << 16);
            hw.y = (uint32_t)__bfloat16_as_ushort(h2) | ((uint32_t)__bfloat16_as_ushort(h3) << 16);
            lw.x = (uint32_t)__bfloat16_as_ushort(l0) | ((uint32_t)__bfloat16_as_ushort(l1) << 16);
            lw.y = (uint32_t)__bfloat16_as_ushort(l2) | ((uint32_t)__bfloat16_as_ushort(l3) << 16);
        }
        *(uint2*)(g_vhi + (size_t)row * DH + lane * 4) = hw;
        *(uint2*)(g_vlo + (size_t)row * DH + lane * 4) = lw;
    }
}

// ---------------------------------------------------------------------------
// FA2 split-bf16 mma.sync flash attention.
// 2 blocks/SM (256-reg budget), software-pipelined LDSM, late V-wait.
// ---------------------------------------------------------------------------
#define SKT_HI 0
#define SKT_LO 18432
#define SV_HI  36864
#define SV_LO  54272
#define ATTN_SMEM 71680
#define KTSTR 144
#define VSTR  272

__global__ __launch_bounds__(128, 2)
void attn_mma_kernel(const float* __restrict__ qin, float* __restrict__ out) {
    const uint32_t sb = smem_u32(sm_dyn);
    const int tid  = threadIdx.x;
    const int lane = tid & 31;
    const int w    = tid >> 5;
    const int bx = blockIdx.x;
    const int h  = bx & 31;
    const int qt = 31 - (bx >> 5);
    const int qglob = qt * 64;

    const int quad = lane >> 2;
    const int qtr  = lane & 3;
    const int r0 = w * 16 + quad;
    const int rowg0 = qglob + r0;
    const int rowg1 = rowg0 + 8;

    const __nv_bfloat16* khi_h = g_khiT + (size_t)h * DH * SEQ;
    const __nv_bfloat16* klo_h = g_kloT + (size_t)h * DH * SEQ;
    const __nv_bfloat16* vhi_h = g_vhi + (size_t)h * SEQ * DH;
    const __nv_bfloat16* vlo_h = g_vlo + (size_t)h * SEQ * DH;

    auto issue_k = [&](int kt) {
        const __nv_bfloat16* kb0 = khi_h + (size_t)kt * 64;
        const __nv_bfloat16* kb1 = klo_h + (size_t)kt * 64;
#pragma unroll
        for (int i = tid; i < 1024; i += 128) {
            int r = i >> 3, c = i & 7;
            uint32_t sa = r * KTSTR + c * 16;
            CP_ASYNC16(sb + SKT_HI + sa, (const uint4*)(kb0 + (size_t)r * SEQ) + c);
            CP_ASYNC16(sb + SKT_LO + sa, (const uint4*)(kb1 + (size_t)r * SEQ) + c);
        }
    };
    auto issue_v = [&](int kt) {
        const uint4* vb0 = (const uint4*)(vhi_h + (size_t)kt * 64 * DH);
        const uint4* vb1 = (const uint4*)(vlo_h + (size_t)kt * 64 * DH);
#pragma unroll
        for (int i = tid; i < 1024; i += 128) {
            int r = i >> 4, c = i & 15;
            uint32_t sa = r * VSTR + c * 16;
            CP_ASYNC16(sb + SV_HI + sa, vb0 + r * 16 + c);
            CP_ASYNC16(sb + SV_LO + sa, vb1 + r * 16 + c);
        }
    };

    issue_k(0);
    CP_COMMIT();

    // ---- stage Q (scaled by 1/sqrt(d)*log2e) fp32, build A-fragments ----
    float* sQf = (float*)(sm_dyn + SV_HI);
    {
        const float sms = 0.12751791677269355f;
        const float4* qbase = (const float4*)(qin + ((size_t)h * SEQ + qglob) * DH);
        for (int i = tid; i < 64 * 32; i += 128) {
            int r = i >> 5, c = i & 31;
            float4 v = qbase[r * 32 + c];
            v.x *= sms; v.y *= sms; v.z *= sms; v.w *= sms;
            *(float4*)&sQf[r * 132 + c * 4] = v;
        }
    }
    __syncthreads();

    uint32_t qhi[8][4], qlo[8][4];
    {
        const float* s0 = &sQf[r0 * 132];
        const float* s1 = &sQf[(r0 + 8) * 132];
#pragma unroll
        for (int kf = 0; kf < 8; ++kf) {
            int k0 = kf * 16 + 2 * qtr;
            float e[4][2] = {{s0[k0], s0[k0 + 1]}, {s1[k0], s1[k0 + 1]},
                             {s0[k0 + 8], s0[k0 + 9]}, {s1[k0 + 8], s1[k0 + 9]}};
#pragma unroll
            for (int j = 0; j < 4; ++j) {
                uint32_t hp = cvtpack(e[j][0], e[j][1]);
                float2 hf = unpack_bf(hp);
                qhi[kf][j] = hp;
                qlo[kf][j] = cvtpack(e[j][0] - hf.x, e[j][1] - hf.y);
            }
        }
    }
    __syncthreads();   // Q staging done; V region may be overwritten now

    const uint32_t kmt_h = sb + SKT_HI + lane * KTSTR;
    const uint32_t kmt_l = sb + SKT_LO + lane * KTSTR;
    const uint32_t vmt_h = sb + SV_HI + lane * VSTR;
    const uint32_t vmt_l = sb + SV_LO + lane * VSTR;

    float O[16][4];
#pragma unroll
    for (int i = 0; i < 16; ++i)
#pragma unroll
        for (int j = 0; j < 4; ++j) O[i][j] = 0.0f;
    float m0 = -INFINITY, m1 = -INFINITY, l0 = 0.0f, l1 = 0.0f;

    for (int kt = 0; kt <= qt; ++kt) {
        issue_v(kt);
        CP_COMMIT();            // in flight: K(kt), V(kt)
        CP_WAIT1();             // K(kt) ready; V(kt) still flying
        __syncthreads();

        // ---- S = Q K^T, software-pipelined LDSM (flat 32 iters) ----
        float Sc[8][4];
#pragma unroll
        for (int nf = 0; nf < 8; ++nf)
            Sc[nf][0] = Sc[nf][1] = Sc[nf][2] = Sc[nf][3] = 0.0f;
        {
            uint32_t bh[4], bl[4], nh[4], nl[4];
            ldmx4t(bh[0], bh[1], bh[2], bh[3], kmt_h);
            ldmx4t(bl[0], bl[1], bl[2], bl[3], kmt_l);
#pragma unroll
            for (int it = 0; it < 32; ++it) {
                const int nf = it >> 2, kf2 = it & 3;
                if (it < 31) {
                    const int nit = it + 1;
                    const uint32_t off = (uint32_t)((nit & 3) * 32 * KTSTR + (nit >> 2) * 16);
                    ldmx4t(nh[0], nh[1], nh[2], nh[3], kmt_h + off);
                    ldmx4t(nl[0], nl[1], nl[2], nl[3], kmt_l + off);
                }
                mma_bf16(Sc[nf], qhi[2 * kf2], bh[0], bh[1]);
                mma_bf16(Sc[nf], qhi[2 * kf2], bl[0], bl[1]);
                mma_bf16(Sc[nf], qlo[2 * kf2], bh[0], bh[1]);
                mma_bf16(Sc[nf], qhi[2 * kf2 + 1], bh[2], bh[3]);
                mma_bf16(Sc[nf], qhi[2 * kf2 + 1], bl[2], bl[3]);
                mma_bf16(Sc[nf], qlo[2 * kf2 + 1], bh[2], bh[3]);
#pragma unroll
                for (int z = 0; z < 4; ++z) { bh[z] = nh[z]; bl[z] = nl[z]; }
            }
        }
        __syncthreads();        // all warps done reading K region

        if (kt < qt) {
            issue_k(kt + 1);    // K(kt+1) under softmax + PV
            CP_COMMIT();        // in flight: V(kt), K(kt+1)
        }

        // ---- causal mask (diagonal tile only) ----
        if (kt == qt) {
            int cb = kt * 64 + 2 * qtr;
#pragma unroll
            for (int nf = 0; nf < 8; ++nf) {
                int c0 = cb + nf * 8, c1 = c0 + 1;
                if (c0 > rowg0) Sc[nf][0] = -1e30f;
                if (c1 > rowg0) Sc[nf][1] = -1e30f;
                if (c0 > rowg1) Sc[nf][2] = -1e30f;
                if (c1 > rowg1) Sc[nf][3] = -1e30f;
            }
        }

        // ---- online softmax (exp2 domain) — overlaps V(kt) load ----
        float t0 = -INFINITY, t1 = -INFINITY;
#pragma unroll
        for (int nf = 0; nf < 8; ++nf) {
            t0 = fmaxf(t0, fmaxf(Sc[nf][0], Sc[nf][1]));
            t1 = fmaxf(t1, fmaxf(Sc[nf][2], Sc[nf][3]));
        }
        t0 = fmaxf(t0, __shfl_xor_sync(0xffffffffu, t0, 1));
        t0 = fmaxf(t0, __shfl_xor_sync(0xffffffffu, t0, 2));
        t1 = fmaxf(t1, __shfl_xor_sync(0xffffffffu, t1, 1));
        t1 = fmaxf(t1, __shfl_xor_sync(0xffffffffu, t1, 2));
        float n0 = fmaxf(m0, t0), n1 = fmaxf(m1, t1);
        float c0 = ex2f(m0 - n0), c1 = ex2f(m1 - n1);
        m0 = n0; m1 = n1;

        float rs0 = 0.0f, rs1 = 0.0f;
#pragma unroll
        for (int nf = 0; nf < 8; ++nf) {
            Sc[nf][0] = ex2f(Sc[nf][0] - n0);
            Sc[nf][1] = ex2f(Sc[nf][1] - n0);
            Sc[nf][2] = ex2f(Sc[nf][2] - n1);
            Sc[nf][3] = ex2f(Sc[nf][3] - n1);
            rs0 += Sc[nf][0] + Sc[nf][1];
            rs1 += Sc[nf][2] + Sc[nf][3];
        }
        rs0 += __shfl_xor_sync(0xffffffffu, rs0, 1);
        rs0 += __shfl_xor_sync(0xffffffffu, rs0, 2);
        rs1 += __shfl_xor_sync(0xffffffffu, rs1, 1);
        rs1 += __shfl_xor_sync(0xffffffffu, rs1, 2);
        l0 = l0 * c0 + rs0;
        l1 = l1 * c1 + rs1;
#pragma unroll
        for (int i = 0; i < 16; ++i) {
            O[i][0] *= c0; O[i][1] *= c0;
            O[i][2] *= c1; O[i][3] *= c1;
        }

        // ---- P fragments ----
        uint32_t phi[4][4], plo[4][4];
#pragma unroll
        for (int kv = 0; kv < 4; ++kv) {
            const float* e0 = Sc[2 * kv];
            const float* e1 = Sc[2 * kv + 1];
            float src[4][2] = {{e0[0], e0[1]}, {e0[2], e0[3]}, {e1[0], e1[1]}, {e1[2], e1[3]}};
#pragma unroll
            for (int j = 0; j < 4; ++j) {
                uint32_t hp = cvtpack(src[j][0], src[j][1]);
                float2 hf = unpack_bf(hp);
                phi[kv][j] = hp;
                plo[kv][j] = cvtpack(src[j][0] - hf.x, src[j][1] - hf.y);
            }
        }

        // ---- now require V(kt) ----
        if (kt < qt) CP_WAIT1();   // V(kt) done, K(kt+1) still flying
        else         CP_WAIT0();   // last tile: only V(qt) outstanding
        __syncthreads();

        // ---- O += P V, software-pipelined LDSM (flat 32 iters) ----
        {
            uint32_t bh[4], bl[4], nh[4], nl[4];
            ldmx4t(bh[0], bh[1], bh[2], bh[3], vmt_h);
            ldmx4t(bl[0], bl[1], bl[2], bl[3], vmt_l);
#pragma unroll
            for (int it = 0; it < 32; ++it) {
                const int nf = it >> 1, kv2 = it & 1;
                if (it < 31) {
                    const int nit = it + 1;
                    const uint32_t off = (uint32_t)((nit & 1) * 32 * VSTR + (nit >> 1) * 16);
                    ldmx4t(nh[0], nh[1], nh[2], nh[3], vmt_h + off);
                    ldmx4t(nl[0], nl[1], nl[2], nl[3], vmt_l + off);
                }
                mma_bf16(O[nf], phi[2 * kv2], bh[0], bh[1]);
                mma_bf16(O[nf], phi[2 * kv2], bl[0], bl[1]);
                mma_bf16(O[nf], plo[2 * kv2], bh[0], bh[1]);
                mma_bf16(O[nf], phi[2 * kv2 + 1], bh[2], bh[3]);
                mma_bf16(O[nf], phi[2 * kv2 + 1], bl[2], bl[3]);
                mma_bf16(O[nf], plo[2 * kv2 + 1], bh[2], bh[3]);
#pragma unroll
                for (int z = 0; z < 4; ++z) { bh[z] = nh[z]; bl[z] = nl[z]; }
            }
        }
        __syncthreads();        // all warps done reading V before next issue_v
    }

    const float i0 = 1.0f / l0, i1 = 1.0f / l1;
    float* ob0 = out + ((size_t)h * SEQ + rowg0) * DH + 2 * qtr;
    float* ob1 = out + ((size_t)h * SEQ + rowg1) * DH + 2 * qtr;
#pragma unroll
    for (int nf = 0; nf < 16; ++nf) {
        float2 a; a.x = O[nf][0] * i0; a.y = O[nf][1] * i0;
        float2 b; b.x = O[nf][2] * i1; b.y = O[nf][3] * i1;
        *(float2*)(ob0 + nf * 8) = a;
        *(float2*)(ob1 + nf * 8) = b;
    }
}

// ---------------------------------------------------------------------------
extern "C" void kernel_launch(void* const* d_in, const int* in_sizes, int n_in,
                              void* d_out, int out_size) {
    const float* q = (const float*)d_in[0];
    const float* k = (const float*)d_in[1];
    const float* v = (const float*)d_in[2];
    float* out = (float*)d_out;

    cudaFuncSetAttribute(prep_kernel, cudaFuncAttributeMaxDynamicSharedMemorySize, PREP_SMEM);
    prep_kernel<<<KQ_BLOCKS + VQ_BLOCKS, 256, PREP_SMEM>>>(k, v);

    cudaFuncSetAttribute(attn_mma_kernel, cudaFuncAttributeMaxDynamicSharedMemorySize, ATTN_SMEM);
    attn_mma_kernel<<<H * 32, 128, ATTN_SMEM>>>(q, out);
}

// round 17
// speedup vs baseline: 2.2349x; 1.0268x over previous
#include <cuda_runtime.h>
#include <cuda_bf16.h>
#include <math.h>
#include <stdint.h>

#define H   32
#define SEQ 2048
#define DH  128
#define NOUT 16
#define QMAXF 7.0f

// ---------------------------------------------------------------------------
// Scratch globals (K^T hi/lo in [h][d][s]; V hi/lo in [h][s][d])
// ---------------------------------------------------------------------------
__device__ __align__(16) __nv_bfloat16 g_khiT[(size_t)H * DH * SEQ];
__device__ __align__(16) __nv_bfloat16 g_kloT[(size_t)H * DH * SEQ];
__device__ __align__(16) __nv_bfloat16 g_vhi[(size_t)H * SEQ * DH];
__device__ __align__(16) __nv_bfloat16 g_vlo[(size_t)H * SEQ * DH];

__device__ __forceinline__ uint32_t cvtpack(float a, float b) {   // {lo=a, hi=b}
    uint32_t r;
    asm("cvt.rn.bf16x2.f32 %0, %2, %1;" : "=r"(r) : "f"(a), "f"(b));
    return r;
}
__device__ __forceinline__ float2 unpack_bf(uint32_t u) {
    __nv_bfloat162 t;
    *reinterpret_cast<uint32_t*>(&t) = u;
    return __bfloat1622float2(t);
}
__device__ __forceinline__ float ex2f(float x) {
    float r;
    asm("ex2.approx.f32 %0, %1;" : "=f"(r) : "f"(x));
    return r;
}
__device__ __forceinline__ uint32_t smem_u32(const void* p) {
    uint32_t a;
    asm("{ .reg .u64 t; cvta.to.shared.u64 t, %1; cvt.u32.u64 %0, t; }" : "=r"(a) : "l"(p));
    return a;
}
__device__ __forceinline__ void ldmx4t(uint32_t& r0, uint32_t& r1, uint32_t& r2, uint32_t& r3,
                                       uint32_t addr) {
    asm volatile("ldmatrix.sync.aligned.m8n8.x4.trans.shared.b16 {%0,%1,%2,%3}, [%4];"
                 : "=r"(r0), "=r"(r1), "=r"(r2), "=r"(r3) : "r"(addr));
}
__device__ __forceinline__ void mma_bf16(float* c, const uint32_t* a, uint32_t b0, uint32_t b1) {
    asm volatile("mma.sync.aligned.m16n8k16.row.col.f32.bf16.bf16.f32 "
                 "{%0,%1,%2,%3}, {%4,%5,%6,%7}, {%8,%9}, {%0,%1,%2,%3};"
                 : "+f"(c[0]), "+f"(c[1]), "+f"(c[2]), "+f"(c[3])
                 : "r"(a[0]), "r"(a[1]), "r"(a[2]), "r"(a[3]), "r"(b0), "r"(b1));
}
#define CP_ASYNC16(dst, src) do { \
    size_t _g = __cvta_generic_to_global((const void*)(src)); \
    asm volatile("cp.async.cg.shared.global [%0], [%1], 16;" :: "r"(dst), "l"(_g) : "memory"); \
} while (0)
#define CP_COMMIT() asm volatile("cp.async.commit_group;" ::: "memory")
#define CP_WAIT0()  asm volatile("cp.async.wait_group 0;" ::: "memory")
#define CP_WAIT1()  asm volatile("cp.async.wait_group 1;" ::: "memory")
#define GBAR64(id)  asm volatile("bar.sync %0, 64;" :: "r"(id) : "memory")

extern __shared__ char sm_dyn[];

// ---------------------------------------------------------------------------
// Fused prep kernel (R15-proven, verbatim).
// ---------------------------------------------------------------------------
#define PREP_SMEM 32768
#define KQ_BLOCKS (H * 32)            // 1024
#define VQ_BLOCKS (H * SEQ / 8)       // 8192

__global__ __launch_bounds__(256, 4) void prep_kernel(const float* __restrict__ kin,
                                                      const float* __restrict__ vin) {
    const int bid = blockIdx.x;
    const int tid = threadIdx.x;

    if (bid < KQ_BLOCKS) {
        float* sabs = (float*)sm_dyn;
        __shared__ float swv[8];
        __shared__ int   swi[8];
        __shared__ int   sgi[4];
        __shared__ float sgv[4];

        const int h = bid >> 5;
        const int d0 = (bid & 31) * 4;
        const int lane = tid & 31, wid = tid >> 5;
        const int g = tid >> 6;
        const int l = tid & 63;

        const float* base = kin + (size_t)h * SEQ * DH + d0;
        float4 vals[8];
#pragma unroll
        for (int j = 0; j < 8; ++j) {
            int r = tid + 256 * j;
            float4 v = *(const float4*)(base + (size_t)r * DH);
            vals[j] = v;
            sabs[0 * SEQ + r] = fabsf(v.x);
            sabs[1 * SEQ + r] = fabsf(v.y);
            sabs[2 * SEQ + r] = fabsf(v.z);
            sabs[3 * SEQ + r] = fabsf(v.w);
        }
        __syncthreads();

        const float* gabs = sabs + g * SEQ;
        float amax = -1.0f; int aidx = 0;
#pragma unroll
        for (int j = 0; j < 32; ++j) {
            int i = l + 64 * j;
            float a = gabs[i];
            if (a > amax) { amax = a; aidx = i; }
        }

        for (int it = 0; it < NOUT; ++it) {
            float bv = amax; int bi = aidx;
#pragma unroll
            for (int o = 16; o > 0; o >>= 1) {
                float ov = __shfl_xor_sync(0xffffffffu, bv, o);
                int   oi = __shfl_xor_sync(0xffffffffu, bi, o);
                if (ov > bv || (ov == bv && oi < bi)) { bv = ov; bi = oi; }
            }
            if (lane == 0) { swv[wid] = bv; swi[wid] = bi; }
            GBAR64(g + 1);
            if (l == 0) {
                float v0 = swv[2 * g], v1 = swv[2 * g + 1];
                int   i0 = swi[2 * g], i1 = swi[2 * g + 1];
                sgi[g] = (v1 > v0 || (v1 == v0 && i1 < i0)) ? i1 : i0;
            }
            GBAR64(g + 1);
            int gw = sgi[g];
            if ((gw & 63) == l) {
                sabs[g * SEQ + gw] = -1.0f;
                amax = -1.0f; aidx = 0;
#pragma unroll
                for (int j = 0; j < 32; ++j) {
                    int i = l + 64 * j;
                    float a = gabs[i];
                    if (a > amax) { amax = a; aidx = i; }
                }
            }
            GBAR64(g + 1);
        }

        {
            float bv = amax;
#pragma unroll
            for (int o = 16; o > 0; o >>= 1) bv = fmaxf(bv, __shfl_xor_sync(0xffffffffu, bv, o));
            if (lane == 0) swv[wid] = bv;
            GBAR64(g + 1);
            if (l == 0) sgv[g] = fmaxf(swv[2 * g], swv[2 * g + 1]);
        }
        __syncthreads();

        float sc[4];
#pragma unroll
        for (int c = 0; c < 4; ++c) sc[c] = fmaxf(sgv[c], 1e-6f) / QMAXF;

#pragma unroll
        for (int j = 0; j < 8; ++j) {
            int r = tid + 256 * j;
            float vv[4] = {vals[j].x, vals[j].y, vals[j].z, vals[j].w};
#pragma unroll
            for (int c = 0; c < 4; ++c) {
                float v = vv[c];
                float o;
                if (sabs[c * SEQ + r] < 0.0f) o = v;
                else {
                    float qq = rintf(__fdiv_rn(v, sc[c]));
                    qq = fminf(fmaxf(qq, -QMAXF), QMAXF);
                    o = qq * sc[c];
                }
                __nv_bfloat16 hi = __float2bfloat16_rn(o);
                __nv_bfloat16 lo = __float2bfloat16_rn(o - __bfloat162float(hi));
                size_t oidx = ((size_t)h * DH + d0 + c) * SEQ + r;
                g_khiT[oidx] = hi;
                g_kloT[oidx] = lo;
            }
        }
    } else {
        const int lane = tid & 31;
        const int row = (bid - KQ_BLOCKS) * 8 + (tid >> 5);

        float4 v4 = *(const float4*)(vin + (size_t)row * DH + lane * 4);
        float vv[4] = {v4.x, v4.y, v4.z, v4.w};
        float av[4] = {fabsf(v4.x), fabsf(v4.y), fabsf(v4.z), fabsf(v4.w)};

        uint32_t omask = 0;
#pragma unroll
        for (int it = 0; it < NOUT; ++it) {
            float bv = -1.0f; int bi = 0x7fffffff;
#pragma unroll
            for (int i = 0; i < 4; ++i)
                if (av[i] > bv) { bv = av[i]; bi = lane * 4 + i; }
#pragma unroll
            for (int o = 16; o > 0; o >>= 1) {
                float ov = __shfl_xor_sync(0xffffffffu, bv, o);
                int   oi = __shfl_xor_sync(0xffffffffu, bi, o);
                if (ov > bv || (ov == bv && oi < bi)) { bv = ov; bi = oi; }
            }
            if ((bi >> 2) == lane) {
                int i = bi & 3;
                omask |= 1u << i;
                av[i] = -1.0f;
            }
        }

        float mx = fmaxf(fmaxf(av[0], av[1]), fmaxf(av[2], av[3]));
#pragma unroll
        for (int o = 16; o > 0; o >>= 1)
            mx = fmaxf(mx, __shfl_xor_sync(0xffffffffu, mx, o));
        const float scale = fmaxf(mx, 1e-6f) / QMAXF;

        float oo[4];
#pragma unroll
        for (int i = 0; i < 4; ++i) {
            float v = vv[i];
            if (omask & (1u << i)) oo[i] = v;
            else {
                float qq = rintf(__fdiv_rn(v, scale));
                qq = fminf(fmaxf(qq, -QMAXF), QMAXF);
                oo[i] = qq * scale;
            }
        }

        uint2 hw, lw;
        {
            __nv_bfloat16 h0 = __float2bfloat16_rn(oo[0]);
            __nv_bfloat16 h1 = __float2bfloat16_rn(oo[1]);
            __nv_bfloat16 h2 = __float2bfloat16_rn(oo[2]);
            __nv_bfloat16 h3 = __float2bfloat16_rn(oo[3]);
            __nv_bfloat16 l0 = __float2bfloat16_rn(oo[0] - __bfloat162float(h0));
            __nv_bfloat16 l1 = __float2bfloat16_rn(oo[1] - __bfloat162float(h1));
            __nv_bfloat16 l2 = __float2bfloat16_rn(oo[2] - __bfloat162float(h2));
            __nv_bfloat16 l3 = __float2bfloat16_rn(oo[3] - __bfloat162float(h3));
            hw.x = (uint32_t)__bfloat16_as_ushort(h0) | ((uint32_t)__bfloat16_as_ushort(h1) << 16);
            hw.y = (uint32_t)__bfloat16_as_ushort(h2) | ((uint32_t)__bfloat16_as_ushort(h3) << 16);
            lw.x = (uint32_t)__bfloat16_as_ushort(l0) | ((uint32_t)__bfloat16_as_ushort(l1) << 16);
            lw.y = (uint32_t)__bfloat16_as_ushort(l2) | ((uint32_t)__bfloat16_as_ushort(l3) << 16);
        }
        *(uint2*)(g_vhi + (size_t)row * DH + lane * 4) = hw;
        *(uint2*)(g_vlo + (size_t)row * DH + lane * 4) = lw;
    }
}

// ---------------------------------------------------------------------------
// FA2 split-bf16 mma.sync flash attention.
// 2 blocks/SM; GEMMs restructured with 4 interleaved accumulators so
// same-accumulator MMAs are spaced by 3 independent ones (hides MMA latency).
// Per-accumulator accumulation order identical to the reference kernel.
// ---------------------------------------------------------------------------
#define SKT_HI 0
#define SKT_LO 18432
#define SV_HI  36864
#define SV_LO  54272
#define ATTN_SMEM 71680
#define KTSTR 144
#define VSTR  272

__global__ __launch_bounds__(128, 2)
void attn_mma_kernel(const float* __restrict__ qin, float* __restrict__ out) {
    const uint32_t sb = smem_u32(sm_dyn);
    const int tid  = threadIdx.x;
    const int lane = tid & 31;
    const int w    = tid >> 5;
    const int bx = blockIdx.x;
    const int h  = bx & 31;
    const int qt = 31 - (bx >> 5);
    const int qglob = qt * 64;

    const int quad = lane >> 2;
    const int qtr  = lane & 3;
    const int r0 = w * 16 + quad;
    const int rowg0 = qglob + r0;
    const int rowg1 = rowg0 + 8;

    const __nv_bfloat16* khi_h = g_khiT + (size_t)h * DH * SEQ;
    const __nv_bfloat16* klo_h = g_kloT + (size_t)h * DH * SEQ;
    const __nv_bfloat16* vhi_h = g_vhi + (size_t)h * SEQ * DH;
    const __nv_bfloat16* vlo_h = g_vlo + (size_t)h * SEQ * DH;

    auto issue_k = [&](int kt) {
        const __nv_bfloat16* kb0 = khi_h + (size_t)kt * 64;
        const __nv_bfloat16* kb1 = klo_h + (size_t)kt * 64;
#pragma unroll
        for (int i = tid; i < 1024; i += 128) {
            int r = i >> 3, c = i & 7;
            uint32_t sa = r * KTSTR + c * 16;
            CP_ASYNC16(sb + SKT_HI + sa, (const uint4*)(kb0 + (size_t)r * SEQ) + c);
            CP_ASYNC16(sb + SKT_LO + sa, (const uint4*)(kb1 + (size_t)r * SEQ) + c);
        }
    };
    auto issue_v = [&](int kt) {
        const uint4* vb0 = (const uint4*)(vhi_h + (size_t)kt * 64 * DH);
        const uint4* vb1 = (const uint4*)(vlo_h + (size_t)kt * 64 * DH);
#pragma unroll
        for (int i = tid; i < 1024; i += 128) {
            int r = i >> 4, c = i & 15;
            uint32_t sa = r * VSTR + c * 16;
            CP_ASYNC16(sb + SV_HI + sa, vb0 + r * 16 + c);
            CP_ASYNC16(sb + SV_LO + sa, vb1 + r * 16 + c);
        }
    };

    issue_k(0);
    CP_COMMIT();

    // ---- stage Q (scaled by 1/sqrt(d)*log2e) fp32, build A-fragments ----
    float* sQf = (float*)(sm_dyn + SV_HI);
    {
        const float sms = 0.12751791677269355f;
        const float4* qbase = (const float4*)(qin + ((size_t)h * SEQ + qglob) * DH);
        for (int i = tid; i < 64 * 32; i += 128) {
            int r = i >> 5, c = i & 31;
            float4 v = qbase[r * 32 + c];
            v.x *= sms; v.y *= sms; v.z *= sms; v.w *= sms;
            *(float4*)&sQf[r * 132 + c * 4] = v;
        }
    }
    __syncthreads();

    uint32_t qhi[8][4], qlo[8][4];
    {
        const float* s0 = &sQf[r0 * 132];
        const float* s1 = &sQf[(r0 + 8) * 132];
#pragma unroll
        for (int kf = 0; kf < 8; ++kf) {
            int k0 = kf * 16 + 2 * qtr;
            float e[4][2] = {{s0[k0], s0[k0 + 1]}, {s1[k0], s1[k0 + 1]},
                             {s0[k0 + 8], s0[k0 + 9]}, {s1[k0 + 8], s1[k0 + 9]}};
#pragma unroll
            for (int j = 0; j < 4; ++j) {
                uint32_t hp = cvtpack(e[j][0], e[j][1]);
                float2 hf = unpack_bf(hp);
                qhi[kf][j] = hp;
                qlo[kf][j] = cvtpack(e[j][0] - hf.x, e[j][1] - hf.y);
            }
        }
    }
    __syncthreads();   // Q staging done; V region may be overwritten now

    const uint32_t kmt_h = sb + SKT_HI + lane * KTSTR;
    const uint32_t kmt_l = sb + SKT_LO + lane * KTSTR;
    const uint32_t vmt_h = sb + SV_HI + lane * VSTR;
    const uint32_t vmt_l = sb + SV_LO + lane * VSTR;

    float O[16][4];
#pragma unroll
    for (int i = 0; i < 16; ++i)
#pragma unroll
        for (int j = 0; j < 4; ++j) O[i][j] = 0.0f;
    float m0 = -INFINITY, m1 = -INFINITY, l0 = 0.0f, l1 = 0.0f;

    for (int kt = 0; kt <= qt; ++kt) {
        issue_v(kt);
        CP_COMMIT();            // in flight: K(kt), V(kt)
        CP_WAIT1();             // K(kt) ready; V(kt) still flying
        __syncthreads();

        // ---- S = Q K^T : kf-major, 4 interleaved accumulators per group ----
        float Sc[8][4];
#pragma unroll
        for (int nf = 0; nf < 8; ++nf)
            Sc[nf][0] = Sc[nf][1] = Sc[nf][2] = Sc[nf][3] = 0.0f;
#pragma unroll
        for (int kf2 = 0; kf2 < 4; ++kf2) {
            const uint32_t koff = (uint32_t)(kf2 * 32 * KTSTR);
            const uint32_t* a0h = qhi[2 * kf2];
            const uint32_t* a0l = qlo[2 * kf2];
            const uint32_t* a1h = qhi[2 * kf2 + 1];
            const uint32_t* a1l = qlo[2 * kf2 + 1];
#pragma unroll
            for (int g = 0; g < 2; ++g) {
                uint32_t bh[4][4], bl[4][4];
#pragma unroll
                for (int q4 = 0; q4 < 4; ++q4) {
                    const uint32_t off = koff + (uint32_t)((g * 4 + q4) * 16);
                    ldmx4t(bh[q4][0], bh[q4][1], bh[q4][2], bh[q4][3], kmt_h + off);
                    ldmx4t(bl[q4][0], bl[q4][1], bl[q4][2], bl[q4][3], kmt_l + off);
                }
                float* S0 = Sc[g * 4 + 0];
                float* S1 = Sc[g * 4 + 1];
                float* S2 = Sc[g * 4 + 2];
                float* S3 = Sc[g * 4 + 3];
                mma_bf16(S0, a0h, bh[0][0], bh[0][1]);
                mma_bf16(S1, a0h, bh[1][0], bh[1][1]);
                mma_bf16(S2, a0h, bh[2][0], bh[2][1]);
                mma_bf16(S3, a0h, bh[3][0], bh[3][1]);
                mma_bf16(S0, a0h, bl[0][0], bl[0][1]);
                mma_bf16(S1, a0h, bl[1][0], bl[1][1]);
                mma_bf16(S2, a0h, bl[2][0], bl[2][1]);
                mma_bf16(S3, a0h, bl[3][0], bl[3][1]);
                mma_bf16(S0, a0l, bh[0][0], bh[0][1]);
                mma_bf16(S1, a0l, bh[1][0], bh[1][1]);
                mma_bf16(S2, a0l, bh[2][0], bh[2][1]);
                mma_bf16(S3, a0l, bh[3][0], bh[3][1]);
                mma_bf16(S0, a1h, bh[0][2], bh[0][3]);
                mma_bf16(S1, a1h, bh[1][2], bh[1][3]);
                mma_bf16(S2, a1h, bh[2][2], bh[2][3]);
                mma_bf16(S3, a1h, bh[3][2], bh[3][3]);
                mma_bf16(S0, a1h, bl[0][2], bl[0][3]);
                mma_bf16(S1, a1h, bl[1][2], bl[1][3]);
                mma_bf16(S2, a1h, bl[2][2], bl[2][3]);
                mma_bf16(S3, a1h, bl[3][2], bl[3][3]);
                mma_bf16(S0, a1l, bh[0][2], bh[0][3]);
                mma_bf16(S1, a1l, bh[1][2], bh[1][3]);
                mma_bf16(S2, a1l, bh[2][2], bh[2][3]);
                mma_bf16(S3, a1l, bh[3][2], bh[3][3]);
            }
        }
        __syncthreads();        // all warps done reading K region

        if (kt < qt) {
            issue_k(kt + 1);    // K(kt+1) under softmax + PV
            CP_COMMIT();        // in flight: V(kt), K(kt+1)
        }

        // ---- causal mask (diagonal tile only) ----
        if (kt == qt) {
            int cb = kt * 64 + 2 * qtr;
#pragma unroll
            for (int nf = 0; nf < 8; ++nf) {
                int c0 = cb + nf * 8, c1 = c0 + 1;
                if (c0 > rowg0) Sc[nf][0] = -1e30f;
                if (c1 > rowg0) Sc[nf][1] = -1e30f;
                if (c0 > rowg1) Sc[nf][2] = -1e30f;
                if (c1 > rowg1) Sc[nf][3] = -1e30f;
            }
        }

        // ---- online softmax (exp2 domain) — overlaps V(kt) load ----
        float t0 = -INFINITY, t1 = -INFINITY;
#pragma unroll
        for (int nf = 0; nf < 8; ++nf) {
            t0 = fmaxf(t0, fmaxf(Sc[nf][0], Sc[nf][1]));
            t1 = fmaxf(t1, fmaxf(Sc[nf][2], Sc[nf][3]));
        }
        t0 = fmaxf(t0, __shfl_xor_sync(0xffffffffu, t0, 1));
        t0 = fmaxf(t0, __shfl_xor_sync(0xffffffffu, t0, 2));
        t1 = fmaxf(t1, __shfl_xor_sync(0xffffffffu, t1, 1));
        t1 = fmaxf(t1, __shfl_xor_sync(0xffffffffu, t1, 2));
        float n0 = fmaxf(m0, t0), n1 = fmaxf(m1, t1);
        float c0 = ex2f(m0 - n0), c1 = ex2f(m1 - n1);
        m0 = n0; m1 = n1;

        float rs0 = 0.0f, rs1 = 0.0f;
#pragma unroll
        for (int nf = 0; nf < 8; ++nf) {
            Sc[nf][0] = ex2f(Sc[nf][0] - n0);
            Sc[nf][1] = ex2f(Sc[nf][1] - n0);
            Sc[nf][2] = ex2f(Sc[nf][2] - n1);
            Sc[nf][3] = ex2f(Sc[nf][3] - n1);
            rs0 += Sc[nf][0] + Sc[nf][1];
            rs1 += Sc[nf][2] + Sc[nf][3];
        }
        rs0 += __shfl_xor_sync(0xffffffffu, rs0, 1);
        rs0 += __shfl_xor_sync(0xffffffffu, rs0, 2);
        rs1 += __shfl_xor_sync(0xffffffffu, rs1, 1);
        rs1 += __shfl_xor_sync(0xffffffffu, rs1, 2);
        l0 = l0 * c0 + rs0;
        l1 = l1 * c1 + rs1;
#pragma unroll
        for (int i = 0; i < 16; ++i) {
            O[i][0] *= c0; O[i][1] *= c0;
            O[i][2] *= c1; O[i][3] *= c1;
        }

        // ---- P fragments ----
        uint32_t phi[4][4], plo[4][4];
#pragma unroll
        for (int kv = 0; kv < 4; ++kv) {
            const float* e0 = Sc[2 * kv];
            const float* e1 = Sc[2 * kv + 1];
            float src[4][2] = {{e0[0], e0[1]}, {e0[2], e0[3]}, {e1[0], e1[1]}, {e1[2], e1[3]}};
#pragma unroll
            for (int j = 0; j < 4; ++j) {
                uint32_t hp = cvtpack(src[j][0], src[j][1]);
                float2 hf = unpack_bf(hp);
                phi[kv][j] = hp;
                plo[kv][j] = cvtpack(src[j][0] - hf.x, src[j][1] - hf.y);
            }
        }

        // ---- now require V(kt) ----
        if (kt < qt) CP_WAIT1();   // V(kt) done, K(kt+1) still flying
        else         CP_WAIT0();   // last tile: only V(qt) outstanding
        __syncthreads();

        // ---- O += P V : kv-major, 4 interleaved accumulators per group ----
#pragma unroll
        for (int kv2 = 0; kv2 < 2; ++kv2) {
            const uint32_t koff = (uint32_t)(kv2 * 32 * VSTR);
            const uint32_t* a0h = phi[2 * kv2];
            const uint32_t* a0l = plo[2 * kv2];
            const uint32_t* a1h = phi[2 * kv2 + 1];
            const uint32_t* a1l = plo[2 * kv2 + 1];
#pragma unroll
            for (int g = 0; g < 4; ++g) {
                uint32_t bh[4][4], bl[4][4];
#pragma unroll
                for (int q4 = 0; q4 < 4; ++q4) {
                    const uint32_t off = koff + (uint32_t)((g * 4 + q4) * 16);
                    ldmx4t(bh[q4][0], bh[q4][1], bh[q4][2], bh[q4][3], vmt_h + off);
                    ldmx4t(bl[q4][0], bl[q4][1], bl[q4][2], bl[q4][3], vmt_l + off);
                }
                float* O0 = O[g * 4 + 0];
                float* O1 = O[g * 4 + 1];
                float* O2 = O[g * 4 + 2];
                float* O3 = O[g * 4 + 3];
                mma_bf16(O0, a0h, bh[0][0], bh[0][1]);
                mma_bf16(O1, a0h, bh[1][0], bh[1][1]);
                mma_bf16(O2, a0h, bh[2][0], bh[2][1]);
                mma_bf16(O3, a0h, bh[3][0], bh[3][1]);
                mma_bf16(O0, a0h, bl[0][0], bl[0][1]);
                mma_bf16(O1, a0h, bl[1][0], bl[1][1]);
                mma_bf16(O2, a0h, bl[2][0], bl[2][1]);
                mma_bf16(O3, a0h, bl[3][0], bl[3][1]);
                mma_bf16(O0, a0l, bh[0][0], bh[0][1]);
                mma_bf16(O1, a0l, bh[1][0], bh[1][1]);
                mma_bf16(O2, a0l, bh[2][0], bh[2][1]);
                mma_bf16(O3, a0l, bh[3][0], bh[3][1]);
                mma_bf16(O0, a1h, bh[0][2], bh[0][3]);
                mma_bf16(O1, a1h, bh[1][2], bh[1][3]);
                mma_bf16(O2, a1h, bh[2][2], bh[2][3]);
                mma_bf16(O3, a1h, bh[3][2], bh[3][3]);
                mma_bf16(O0, a1h, bl[0][2], bl[0][3]);
                mma_bf16(O1, a1h, bl[1][2], bl[1][3]);
                mma_bf16(O2, a1h, bl[2][2], bl[2][3]);
                mma_bf16(O3, a1h, bl[3][2], bl[3][3]);
                mma_bf16(O0, a1l, bh[0][2], bh[0][3]);
                mma_bf16(O1, a1l, bh[1][2], bh[1][3]);
                mma_bf16(O2, a1l, bh[2][2], bh[2][3]);
                mma_bf16(O3, a1l, bh[3][2], bh[3][3]);
            }
        }
        __syncthreads();        // all warps done reading V before next issue_v
    }

    const float i0 = 1.0f / l0, i1 = 1.0f / l1;
    float* ob0 = out + ((size_t)h * SEQ + rowg0) * DH + 2 * qtr;
    float* ob1 = out + ((size_t)h * SEQ + rowg1) * DH + 2 * qtr;
#pragma unroll
    for (int nf = 0; nf < 16; ++nf) {
        float2 a; a.x = O[nf][0] * i0; a.y = O[nf][1] * i0;
        float2 b; b.x = O[nf][2] * i1; b.y = O[nf][3] * i1;
        *(float2*)(ob0 + nf * 8) = a;
        *(float2*)(ob1 + nf * 8) = b;
    }
}

// ---------------------------------------------------------------------------
extern "C" void kernel_launch(void* const* d_in, const int* in_sizes, int n_in,
                              void* d_out, int out_size) {
    const float* q = (const float*)d_in[0];
    const float* k = (const float*)d_in[1];
    const float* v = (const float*)d_in[2];
    float* out = (float*)d_out;

    cudaFuncSetAttribute(prep_kernel, cudaFuncAttributeMaxDynamicSharedMemorySize, PREP_SMEM);
    prep_kernel<<<KQ_BLOCKS + VQ_BLOCKS, 256, PREP_SMEM>>>(k, v);

    cudaFuncSetAttribute(attn_mma_kernel, cudaFuncAttributeMaxDynamicSharedMemorySize, ATTN_SMEM);
    attn_mma_kernel<<<H * 32, 128, ATTN_SMEM>>>(q, out);
}